// round 4
// baseline (speedup 1.0000x reference)
#include <cuda_runtime.h>
#include <math.h>

// ---------------------------------------------------------------------------
// Problem constants
// ---------------------------------------------------------------------------
static constexpr int Bn   = 48;
static constexpr int Ln   = 512;
static constexpr int Dn   = 192;
static constexpr int Hn   = 6;
static constexpr int DKn  = 32;
static constexpr int HIDn = 768;
static constexpr int ROWS = Bn * Ln;                         // 24576
static constexpr long long BLD = (long long)ROWS * Dn;       // 4,718,592
static constexpr long long SZ_HID = (long long)ROWS * HIDn;  // 18,874,368
static constexpr float SCALE = 0.17677669529663689f;         // 1/sqrt(32)
static constexpr float EPSf  = 1e-5f;

// ---------------------------------------------------------------------------
// Static device scratch: 18 BLD buffers + 2 hidden buffers
// ---------------------------------------------------------------------------
static constexpr long long WS_FLOATS = 18 * BLD + 2 * SZ_HID;
__device__ float g_ws[WS_FLOATS];

// ---------------------------------------------------------------------------
// f32x2 packed helpers
// ---------------------------------------------------------------------------
typedef unsigned long long ull;

__device__ __forceinline__ ull pk2(float lo, float hi) {
    ull r; asm("mov.b64 %0, {%1,%2};" : "=l"(r) : "f"(lo), "f"(hi)); return r;
}
__device__ __forceinline__ void upk2(ull v, float& lo, float& hi) {
    asm("mov.b64 {%0,%1}, %2;" : "=f"(lo), "=f"(hi) : "l"(v));
}
__device__ __forceinline__ ull ffma2(ull a, ull b, ull c) {
    ull d; asm("fma.rn.f32x2 %0, %1, %2, %3;" : "=l"(d) : "l"(a), "l"(b), "l"(c)); return d;
}
__device__ __forceinline__ ull fmul2(ull a, ull b) {
    ull d; asm("mul.rn.f32x2 %0, %1, %2;" : "=l"(d) : "l"(a), "l"(b)); return d;
}

// ---------------------------------------------------------------------------
// Masked LayerNorm (optional fused residual). One warp per row.
// ---------------------------------------------------------------------------
__device__ __forceinline__ void mln_row(const float* __restrict__ xr,
                                        const float* __restrict__ rr,
                                        bool ok,
                                        const float* __restrict__ gamma,
                                        const float* __restrict__ beta,
                                        float* __restrict__ out_r,
                                        int lane, float* vout /*6, may be null*/)
{
    float v[6];
    float s = 0.f;
#pragma unroll
    for (int e = 0; e < 6; e++) {
        int idx = lane + 32 * e;
        float t = xr[idx];
        if (rr) t += rr[idx];
        v[e] = t; s += t;
    }
    float s2 = 0.f;
#pragma unroll
    for (int e = 0; e < 6; e++) s2 += v[e] * v[e];
#pragma unroll
    for (int o = 16; o > 0; o >>= 1) {
        s  += __shfl_xor_sync(0xffffffffu, s,  o);
        s2 += __shfl_xor_sync(0xffffffffu, s2, o);
    }
    float mu   = s * (1.f / Dn);
    float var  = s2 * (1.f / Dn) - mu * mu;
    float rstd = rsqrtf(var + EPSf);
#pragma unroll
    for (int e = 0; e < 6; e++) {
        int idx = lane + 32 * e;
        float o_ = ok ? fmaf((v[e] - mu) * rstd, gamma[idx], beta[idx]) : v[e];
        out_r[idx] = o_;
        if (vout) vout[e] = o_;
    }
}

__global__ void mln_kernel(const float* __restrict__ x,
                           const float* __restrict__ res,
                           const unsigned int* __restrict__ valid,
                           const float* __restrict__ gamma,
                           const float* __restrict__ beta,
                           float* __restrict__ out)
{
    int warp = threadIdx.x >> 5, lane = threadIdx.x & 31;
    int row  = blockIdx.x * 8 + warp;
    mln_row(x + (long long)row * Dn, res ? res + (long long)row * Dn : nullptr,
            valid[row] != 0u, gamma, beta, out + (long long)row * Dn, lane, nullptr);
}

// fused: o = mln(x+res); xn = mln(o)   (post-attn LN then pre-FFN LN)
__global__ void mln2_kernel(const float* __restrict__ x,
                            const float* __restrict__ res,
                            const unsigned int* __restrict__ valid,
                            const float* __restrict__ g1, const float* __restrict__ b1,
                            const float* __restrict__ g2, const float* __restrict__ b2,
                            float* __restrict__ o_out, float* __restrict__ xn_out)
{
    int warp = threadIdx.x >> 5, lane = threadIdx.x & 31;
    int row  = blockIdx.x * 8 + warp;
    bool ok = valid[row] != 0u;
    float v[6];
    mln_row(x + (long long)row * Dn, res + (long long)row * Dn,
            ok, g1, b1, o_out + (long long)row * Dn, lane, v);
    // second LN on v (registers)
    float s = 0.f, s2 = 0.f;
#pragma unroll
    for (int e = 0; e < 6; e++) { s += v[e]; s2 += v[e] * v[e]; }
#pragma unroll
    for (int o = 16; o > 0; o >>= 1) {
        s  += __shfl_xor_sync(0xffffffffu, s,  o);
        s2 += __shfl_xor_sync(0xffffffffu, s2, o);
    }
    float mu = s * (1.f / Dn);
    float var = s2 * (1.f / Dn) - mu * mu;
    float rstd = rsqrtf(var + EPSf);
#pragma unroll
    for (int e = 0; e < 6; e++) {
        int idx = lane + 32 * e;
        float o_ = ok ? fmaf((v[e] - mu) * rstd, g2[idx], b2[idx]) : v[e];
        xn_out[(long long)row * Dn + idx] = o_;
    }
}

// ---------------------------------------------------------------------------
// Batched FFMA2 GEMM: C[z] = A[z] @ W[z] + bias[z], EPI=1: exact GELU.
// Tile 128x64, BK=16, 256 threads, microtile 8rows x 4cols.
// Row-paired accumulators: A pairs load directly; B duplicated in smem.
// Coalesced epilogue via smem staging.
// ---------------------------------------------------------------------------
struct GemmBatch {
    const float* A[6];
    const float* W[6];
    const float* bias[6];
    float* C[6];
};

template <int EPI>
__global__ __launch_bounds__(256) void gemm_f2_kernel(
    GemmBatch g, int M, int N, int K)
{
    __shared__ __align__(16) float sm[9216];   // 36 KB
    float (*As)[16][136] = (float(*)[16][136])sm;            // [buf][k][m]
    float (*Bs)[16][136] = (float(*)[16][136])(sm + 4352);   // [buf][k][2n dup]

    const int z = blockIdx.z;
    const float* __restrict__ A = g.A[z];
    const float* __restrict__ W = g.W[z];
    const float* __restrict__ bias = g.bias[z];
    float* __restrict__ C = g.C[z];

    const int tid = threadIdx.x;
    const int tx = tid & 15, ty = tid >> 4;
    const int bm = blockIdx.x * 128, bn = blockIdx.y * 64;

    const int arow = tid >> 1, ak = (tid & 1) * 8;   // A loader
    const int bk   = tid >> 4, bc = (tid & 15) * 4;  // B loader

    const float* gA = A + (long long)(bm + arow) * K + ak;
    const float* gB = W + (long long)bk * N + bn + bc;

    float ar[8];
    float4 bstage;

    // prologue: tile 0 -> buf 0
    *(float4*)&ar[0] = *(const float4*)(gA);
    *(float4*)&ar[4] = *(const float4*)(gA + 4);
    bstage = *(const float4*)(gB);
#pragma unroll
    for (int c = 0; c < 8; c++) As[0][ak + c][arow] = ar[c];
    *(float4*)&Bs[0][bk][2 * bc]     = make_float4(bstage.x, bstage.x, bstage.y, bstage.y);
    *(float4*)&Bs[0][bk][2 * bc + 4] = make_float4(bstage.z, bstage.z, bstage.w, bstage.w);

    ull acc[4][4];
#pragma unroll
    for (int r = 0; r < 4; r++)
#pragma unroll
        for (int c = 0; c < 4; c++) acc[r][c] = 0ull;

    const int T = K >> 4;
    for (int t = 0; t < T; t++) {
        __syncthreads();
        const int buf = t & 1;
        if (t + 1 < T) {
            *(float4*)&ar[0] = *(const float4*)(gA + (t + 1) * 16);
            *(float4*)&ar[4] = *(const float4*)(gA + (t + 1) * 16 + 4);
            bstage = *(const float4*)(gB + (long long)(t + 1) * 16 * N);
        }
#pragma unroll
        for (int k = 0; k < 16; k++) {
            const ull* ap = (const ull*)&As[buf][k][ty * 8];   // 4 row-pairs
            const ull* bp = (const ull*)&Bs[buf][k][tx * 8];   // 4 dup cols
            ull a0 = ap[0], a1 = ap[1], a2 = ap[2], a3 = ap[3];
            ull b0 = bp[0], b1 = bp[1], b2 = bp[2], b3 = bp[3];
            acc[0][0] = ffma2(a0, b0, acc[0][0]); acc[0][1] = ffma2(a0, b1, acc[0][1]);
            acc[0][2] = ffma2(a0, b2, acc[0][2]); acc[0][3] = ffma2(a0, b3, acc[0][3]);
            acc[1][0] = ffma2(a1, b0, acc[1][0]); acc[1][1] = ffma2(a1, b1, acc[1][1]);
            acc[1][2] = ffma2(a1, b2, acc[1][2]); acc[1][3] = ffma2(a1, b3, acc[1][3]);
            acc[2][0] = ffma2(a2, b0, acc[2][0]); acc[2][1] = ffma2(a2, b1, acc[2][1]);
            acc[2][2] = ffma2(a2, b2, acc[2][2]); acc[2][3] = ffma2(a2, b3, acc[2][3]);
            acc[3][0] = ffma2(a3, b0, acc[3][0]); acc[3][1] = ffma2(a3, b1, acc[3][1]);
            acc[3][2] = ffma2(a3, b2, acc[3][2]); acc[3][3] = ffma2(a3, b3, acc[3][3]);
        }
        if (t + 1 < T) {
            const int nb = buf ^ 1;
#pragma unroll
            for (int c = 0; c < 8; c++) As[nb][ak + c][arow] = ar[c];
            *(float4*)&Bs[nb][bk][2 * bc]     = make_float4(bstage.x, bstage.x, bstage.y, bstage.y);
            *(float4*)&Bs[nb][bk][2 * bc + 4] = make_float4(bstage.z, bstage.z, bstage.w, bstage.w);
        }
    }

    __syncthreads();   // done with As/Bs; reuse sm as epilogue stage [128][72]
    float4 b4 = *(const float4*)(bias + bn + tx * 4);
#pragma unroll
    for (int c = 0; c < 4; c++) {
        float bv = (c == 0) ? b4.x : (c == 1) ? b4.y : (c == 2) ? b4.z : b4.w;
#pragma unroll
        for (int r = 0; r < 4; r++) {
            float e0, e1;
            upk2(acc[r][c], e0, e1);
            e0 += bv; e1 += bv;
            if (EPI == 1) { e0 *= normcdff(e0); e1 *= normcdff(e1); }
            sm[(ty * 8 + 2 * r)     * 72 + tx * 4 + c] = e0;
            sm[(ty * 8 + 2 * r + 1) * 72 + tx * 4 + c] = e1;
        }
    }
    __syncthreads();
    const int mrow = tid >> 1, half = (tid & 1) * 32;
#pragma unroll
    for (int q = 0; q < 8; q++) {
        float4 v = *(const float4*)&sm[mrow * 72 + half + q * 4];
        *(float4*)(C + (long long)(bm + mrow) * N + bn + half + q * 4) = v;
    }
}

// ---------------------------------------------------------------------------
// Flash attention, batched over direction (blockIdx.z).
// ---------------------------------------------------------------------------
struct FlashArgs {
    const float* Q[2];
    const float* K[2];
    const float* V[2];
    const unsigned int* vq[2];
    const unsigned int* vk[2];
    float* ctx[2];
};

__global__ __launch_bounds__(256) void flash_kernel(FlashArgs fa)
{
    __shared__ __align__(16) float Qs2[32][136];  // scaled + duplicated over m
    __shared__ __align__(16) float Ks[32][68];    // [d][n]
    __shared__ __align__(16) float Vs[64][34];    // [j][d]
    __shared__ __align__(16) float Ps2[64][136];  // duplicated over j
    __shared__ unsigned char vqs[64];
    __shared__ unsigned char vks[64];

    const int tid = threadIdx.x;
    const int tx = tid & 15, ty = tid >> 4;
    const int qt = blockIdx.x;
    const int bh = blockIdx.y;
    const int z  = blockIdx.z;
    const int b = bh / Hn, h = bh % Hn;

    const float* Qb = fa.Q[z] + (long long)b * Ln * Dn + h * DKn;
    const float* Kb = fa.K[z] + (long long)b * Ln * Dn + h * DKn;
    const float* Vb = fa.V[z] + (long long)b * Ln * Dn + h * DKn;
    const unsigned int* vq = fa.vq[z];
    const unsigned int* vk = fa.vk[z];
    float* ctx = fa.ctx[z];

    const int ld = tid & 31, lr = tid >> 5;

#pragma unroll
    for (int i = 0; i < 8; i++) {
        int r = lr + i * 8;
        float qv = Qb[(long long)(qt * 64 + r) * Dn + ld] * SCALE;
        *(float2*)&Qs2[ld][2 * r] = make_float2(qv, qv);
        Ks[ld][r] = Kb[(long long)r * Dn + ld];
        Vs[r][ld] = Vb[(long long)r * Dn + ld];
    }
    if (tid < 64)       vqs[tid]      = (vq[b * Ln + qt * 64 + tid] != 0u) ? 1 : 0;
    else if (tid < 128) vks[tid - 64] = (vk[b * Ln + tid - 64]      != 0u) ? 1 : 0;
    __syncthreads();

    ull   o2[4]   = {0ull, 0ull, 0ull, 0ull};
    float mrow[4] = {-INFINITY, -INFINITY, -INFINITY, -INFINITY};
    float lrow[4] = {0.f, 0.f, 0.f, 0.f};

    float kreg[8], vreg[8];
    unsigned int vkr = 0u;

    for (int t = 0; t < 8; t++) {
        // ---- S = Qs2 . K^T ----
        ull s01[4] = {0ull, 0ull, 0ull, 0ull};
        ull s23[4] = {0ull, 0ull, 0ull, 0ull};
#pragma unroll
        for (int k = 0; k < 32; k++) {
            const ull* qp = (const ull*)&Qs2[k][ty * 8];   // dup pairs rows i=0..3
            const ull* bp = (const ull*)&Ks[k][tx * 4];
            ull b01 = bp[0], b23 = bp[1];
            ull q0 = qp[0], q1 = qp[1], q2 = qp[2], q3 = qp[3];
            s01[0] = ffma2(q0, b01, s01[0]); s23[0] = ffma2(q0, b23, s23[0]);
            s01[1] = ffma2(q1, b01, s01[1]); s23[1] = ffma2(q1, b23, s23[1]);
            s01[2] = ffma2(q2, b01, s01[2]); s23[2] = ffma2(q2, b23, s23[2]);
            s01[3] = ffma2(q3, b01, s01[3]); s23[3] = ffma2(q3, b23, s23[3]);
        }

        // ---- prefetch next K/V tile ----
        if (t < 7) {
#pragma unroll
            for (int i = 0; i < 8; i++) {
                int r = (t + 1) * 64 + lr + i * 8;
                kreg[i] = Kb[(long long)r * Dn + ld];
                vreg[i] = Vb[(long long)r * Dn + ld];
            }
            if (tid < 64) vkr = vk[b * Ln + (t + 1) * 64 + tid];
        }

        // ---- mask + online softmax; store duplicated P ----
        float s[4][4];
#pragma unroll
        for (int i = 0; i < 4; i++) {
            upk2(s01[i], s[i][0], s[i][1]);
            upk2(s23[i], s[i][2], s[i][3]);
            bool qok = vqs[ty * 4 + i] != 0;
#pragma unroll
            for (int j = 0; j < 4; j++)
                if (!(qok && vks[tx * 4 + j])) s[i][j] = -1e9f;
        }
#pragma unroll
        for (int i = 0; i < 4; i++) {
            float tm = fmaxf(fmaxf(s[i][0], s[i][1]), fmaxf(s[i][2], s[i][3]));
#pragma unroll
            for (int o = 8; o > 0; o >>= 1)
                tm = fmaxf(tm, __shfl_xor_sync(0xffffffffu, tm, o));
            float nm = fmaxf(mrow[i], tm);
            float p0 = __expf(s[i][0] - nm);
            float p1 = __expf(s[i][1] - nm);
            float p2 = __expf(s[i][2] - nm);
            float p3 = __expf(s[i][3] - nm);
            float ts = (p0 + p1) + (p2 + p3);
#pragma unroll
            for (int o = 8; o > 0; o >>= 1)
                ts += __shfl_xor_sync(0xffffffffu, ts, o);
            float fac = __expf(mrow[i] - nm);
            lrow[i] = lrow[i] * fac + ts;
            mrow[i] = nm;
            o2[i] = fmul2(o2[i], pk2(fac, fac));
            *(float4*)&Ps2[ty * 4 + i][8 * tx]     = make_float4(p0, p0, p1, p1);
            *(float4*)&Ps2[ty * 4 + i][8 * tx + 4] = make_float4(p2, p2, p3, p3);
        }
        __syncthreads();

        // ---- O += P @ V ----
#pragma unroll 4
        for (int jj = 0; jj < 64; jj += 2) {
            ull v0 = *(const ull*)&Vs[jj][tx * 2];
            ull v1 = *(const ull*)&Vs[jj + 1][tx * 2];
#pragma unroll
            for (int i = 0; i < 4; i++) {
                const ull* pp = (const ull*)&Ps2[ty * 4 + i][2 * jj];
                o2[i] = ffma2(pp[0], v0, o2[i]);
                o2[i] = ffma2(pp[1], v1, o2[i]);
            }
        }
        __syncthreads();

        if (t < 7) {
#pragma unroll
            for (int i = 0; i < 8; i++) {
                int r = lr + i * 8;
                Ks[ld][r] = kreg[i];
                Vs[r][ld] = vreg[i];
            }
            if (tid < 64) vks[tid] = (vkr != 0u) ? 1 : 0;
            __syncthreads();
        }
    }

#pragma unroll
    for (int i = 0; i < 4; i++) {
        float o0, o1;
        upk2(o2[i], o0, o1);
        float inv = 1.f / lrow[i];
        long long row = (long long)b * Ln + qt * 64 + ty * 4 + i;
        *(float2*)(ctx + row * Dn + h * DKn + tx * 2) = make_float2(o0 * inv, o1 * inv);
    }
}

// ---------------------------------------------------------------------------
// Host launcher
// ---------------------------------------------------------------------------
extern "C" void kernel_launch(void* const* d_in, const int* in_sizes, int n_in,
                              void* d_out, int out_size)
{
    const float* x_a = (const float*)d_in[0];
    const float* x_b = (const float*)d_in[1];
    const unsigned int* valid_a = (const unsigned int*)d_in[2];
    const unsigned int* valid_b = (const unsigned int*)d_in[3];
    const float* ln_a_g  = (const float*)d_in[4];
    const float* ln_a_b  = (const float*)d_in[5];
    const float* ln_b_g  = (const float*)d_in[6];
    const float* ln_b_b  = (const float*)d_in[7];
    const float* ln_oa_g = (const float*)d_in[8];
    const float* ln_oa_b = (const float*)d_in[9];
    const float* ln_ob_g = (const float*)d_in[10];
    const float* ln_ob_b = (const float*)d_in[11];
    const float* wq = (const float*)d_in[12];
    const float* bq = (const float*)d_in[13];
    const float* wk = (const float*)d_in[14];
    const float* bk = (const float*)d_in[15];
    const float* wv = (const float*)d_in[16];
    const float* bv = (const float*)d_in[17];
    const float* wo = (const float*)d_in[18];
    const float* bo = (const float*)d_in[19];
    const float* fln_g  = (const float*)d_in[20];
    const float* fln_b  = (const float*)d_in[21];
    const float* flno_g = (const float*)d_in[22];
    const float* flno_b = (const float*)d_in[23];
    const float* w1 = (const float*)d_in[24];
    const float* b1 = (const float*)d_in[25];
    const float* w2 = (const float*)d_in[26];
    const float* b2 = (const float*)d_in[27];

    float* ws = nullptr;
    cudaGetSymbolAddress((void**)&ws, g_ws);

    float* aln  = ws + 0 * BLD;
    float* bln  = ws + 1 * BLD;
    float* Qa   = ws + 2 * BLD;
    float* Ka   = ws + 3 * BLD;
    float* Va   = ws + 4 * BLD;
    float* Qb   = ws + 5 * BLD;
    float* Kb   = ws + 6 * BLD;
    float* Vb   = ws + 7 * BLD;
    float* ctxa = ws + 8 * BLD;
    float* ctxb = ws + 9 * BLD;
    float* tmpa = ws + 10 * BLD;
    float* tmpb = ws + 11 * BLD;
    float* oa   = ws + 12 * BLD;
    float* ob   = ws + 13 * BLD;
    float* xna  = ws + 14 * BLD;
    float* xnb  = ws + 15 * BLD;
    float* yba  = ws + 16 * BLD;
    float* ybb  = ws + 17 * BLD;
    float* hida = ws + 18 * BLD;
    float* hidb = hida + SZ_HID;

    float* out_a = (float*)d_out;
    float* out_b = (float*)d_out + BLD;

    dim3 blk(256);
    dim3 gLN(ROWS / 8);

    // 1. pre-attention masked LN
    mln_kernel<<<gLN, blk>>>(x_a, nullptr, valid_a, ln_a_g, ln_a_b, aln);
    mln_kernel<<<gLN, blk>>>(x_b, nullptr, valid_b, ln_b_g, ln_b_b, bln);

    // 2. six projections, one batched launch
    {
        GemmBatch g;
        g.A[0] = aln; g.A[1] = aln; g.A[2] = aln;
        g.A[3] = bln; g.A[4] = bln; g.A[5] = bln;
        g.W[0] = wq;  g.W[1] = wk;  g.W[2] = wv;
        g.W[3] = wq;  g.W[4] = wk;  g.W[5] = wv;
        g.bias[0] = bq; g.bias[1] = bk; g.bias[2] = bv;
        g.bias[3] = bq; g.bias[4] = bk; g.bias[5] = bv;
        g.C[0] = Qa; g.C[1] = Ka; g.C[2] = Va;
        g.C[3] = Qb; g.C[4] = Kb; g.C[5] = Vb;
        dim3 grid(ROWS / 128, Dn / 64, 6);
        gemm_f2_kernel<0><<<grid, blk>>>(g, ROWS, Dn, Dn);
    }

    // 3. flash attention, both directions in one launch
    {
        FlashArgs fa;
        fa.Q[0] = Qa; fa.K[0] = Kb; fa.V[0] = Vb; fa.vq[0] = valid_a; fa.vk[0] = valid_b; fa.ctx[0] = ctxa;
        fa.Q[1] = Qb; fa.K[1] = Ka; fa.V[1] = Va; fa.vq[1] = valid_b; fa.vk[1] = valid_a; fa.ctx[1] = ctxb;
        dim3 grid(Ln / 64, Bn * Hn, 2);
        flash_kernel<<<grid, blk>>>(fa);
    }

    // 4. output projection (batched) + fused residual-LN + pre-FFN LN
    {
        GemmBatch g = {};
        g.A[0] = ctxa; g.A[1] = ctxb;
        g.W[0] = wo;   g.W[1] = wo;
        g.bias[0] = bo; g.bias[1] = bo;
        g.C[0] = tmpa; g.C[1] = tmpb;
        dim3 grid(ROWS / 128, Dn / 64, 2);
        gemm_f2_kernel<0><<<grid, blk>>>(g, ROWS, Dn, Dn);
    }
    mln2_kernel<<<gLN, blk>>>(tmpa, x_a, valid_a, ln_oa_g, ln_oa_b, fln_g, fln_b, oa, xna);
    mln2_kernel<<<gLN, blk>>>(tmpb, x_b, valid_b, ln_ob_g, ln_ob_b, fln_g, fln_b, ob, xnb);

    // 5. FFN w1 (GELU) batched
    {
        GemmBatch g = {};
        g.A[0] = xna; g.A[1] = xnb;
        g.W[0] = w1;  g.W[1] = w1;
        g.bias[0] = b1; g.bias[1] = b1;
        g.C[0] = hida; g.C[1] = hidb;
        dim3 grid(ROWS / 128, HIDn / 64, 2);
        gemm_f2_kernel<1><<<grid, blk>>>(g, ROWS, HIDn, Dn);
    }
    // 6. FFN w2 batched
    {
        GemmBatch g = {};
        g.A[0] = hida; g.A[1] = hidb;
        g.W[0] = w2;   g.W[1] = w2;
        g.bias[0] = b2; g.bias[1] = b2;
        g.C[0] = yba;  g.C[1] = ybb;
        dim3 grid(ROWS / 128, Dn / 64, 2);
        gemm_f2_kernel<0><<<grid, blk>>>(g, ROWS, Dn, HIDn);
    }
    // 7. final masked LN (+residual)
    mln_kernel<<<gLN, blk>>>(yba, oa, valid_a, flno_g, flno_b, out_a);
    mln_kernel<<<gLN, blk>>>(ybb, ob, valid_b, flno_g, flno_b, out_b);
}

// round 5
// speedup vs baseline: 1.5001x; 1.5001x over previous
#include <cuda_runtime.h>
#include <math.h>

// ---------------------------------------------------------------------------
// Problem constants
// ---------------------------------------------------------------------------
static constexpr int Bn   = 48;
static constexpr int Ln   = 512;
static constexpr int Dn   = 192;
static constexpr int Hn   = 6;
static constexpr int DKn  = 32;
static constexpr int HIDn = 768;
static constexpr int ROWS = Bn * Ln;                         // 24576
static constexpr long long BLD = (long long)ROWS * Dn;       // 4,718,592
static constexpr long long SZ_HID = (long long)ROWS * HIDn;  // 18,874,368
static constexpr float SCALE = 0.17677669529663689f;         // 1/sqrt(32)
static constexpr float EPSf  = 1e-5f;

// ---------------------------------------------------------------------------
// Static device scratch: 18 BLD buffers + 2 hidden buffers
// ---------------------------------------------------------------------------
static constexpr long long WS_FLOATS = 18 * BLD + 2 * SZ_HID;
__device__ float g_ws[WS_FLOATS];

// ---------------------------------------------------------------------------
// f32x2 packed helpers
// ---------------------------------------------------------------------------
typedef unsigned long long ull;

__device__ __forceinline__ ull pk2(float lo, float hi) {
    ull r; asm("mov.b64 %0, {%1,%2};" : "=l"(r) : "f"(lo), "f"(hi)); return r;
}
__device__ __forceinline__ void upk2(ull v, float& lo, float& hi) {
    asm("mov.b64 {%0,%1}, %2;" : "=f"(lo), "=f"(hi) : "l"(v));
}
__device__ __forceinline__ ull ffma2(ull a, ull b, ull c) {
    ull d; asm("fma.rn.f32x2 %0, %1, %2, %3;" : "=l"(d) : "l"(a), "l"(b), "l"(c)); return d;
}
__device__ __forceinline__ ull fmul2(ull a, ull b) {
    ull d; asm("mul.rn.f32x2 %0, %1, %2;" : "=l"(d) : "l"(a), "l"(b)); return d;
}

// ---------------------------------------------------------------------------
// Masked LayerNorm (optional fused residual). One warp per row.
// ---------------------------------------------------------------------------
__device__ __forceinline__ void mln_row(const float* __restrict__ xr,
                                        const float* __restrict__ rr,
                                        bool ok,
                                        const float* __restrict__ gamma,
                                        const float* __restrict__ beta,
                                        float* __restrict__ out_r,
                                        int lane, float* vout /*6, may be null*/)
{
    float v[6];
    float s = 0.f;
#pragma unroll
    for (int e = 0; e < 6; e++) {
        int idx = lane + 32 * e;
        float t = xr[idx];
        if (rr) t += rr[idx];
        v[e] = t; s += t;
    }
    float s2 = 0.f;
#pragma unroll
    for (int e = 0; e < 6; e++) s2 += v[e] * v[e];
#pragma unroll
    for (int o = 16; o > 0; o >>= 1) {
        s  += __shfl_xor_sync(0xffffffffu, s,  o);
        s2 += __shfl_xor_sync(0xffffffffu, s2, o);
    }
    float mu   = s * (1.f / Dn);
    float var  = s2 * (1.f / Dn) - mu * mu;
    float rstd = rsqrtf(var + EPSf);
#pragma unroll
    for (int e = 0; e < 6; e++) {
        int idx = lane + 32 * e;
        float o_ = ok ? fmaf((v[e] - mu) * rstd, gamma[idx], beta[idx]) : v[e];
        out_r[idx] = o_;
        if (vout) vout[e] = o_;
    }
}

__global__ void mln_kernel(const float* __restrict__ x,
                           const float* __restrict__ res,
                           const unsigned int* __restrict__ valid,
                           const float* __restrict__ gamma,
                           const float* __restrict__ beta,
                           float* __restrict__ out)
{
    int warp = threadIdx.x >> 5, lane = threadIdx.x & 31;
    int row  = blockIdx.x * 8 + warp;
    mln_row(x + (long long)row * Dn, res ? res + (long long)row * Dn : nullptr,
            valid[row] != 0u, gamma, beta, out + (long long)row * Dn, lane, nullptr);
}

// fused: o = mln(x+res); xn = mln(o)
__global__ void mln2_kernel(const float* __restrict__ x,
                            const float* __restrict__ res,
                            const unsigned int* __restrict__ valid,
                            const float* __restrict__ g1, const float* __restrict__ b1,
                            const float* __restrict__ g2, const float* __restrict__ b2,
                            float* __restrict__ o_out, float* __restrict__ xn_out)
{
    int warp = threadIdx.x >> 5, lane = threadIdx.x & 31;
    int row  = blockIdx.x * 8 + warp;
    bool ok = valid[row] != 0u;
    float v[6];
    mln_row(x + (long long)row * Dn, res + (long long)row * Dn,
            ok, g1, b1, o_out + (long long)row * Dn, lane, v);
    float s = 0.f, s2 = 0.f;
#pragma unroll
    for (int e = 0; e < 6; e++) { s += v[e]; s2 += v[e] * v[e]; }
#pragma unroll
    for (int o = 16; o > 0; o >>= 1) {
        s  += __shfl_xor_sync(0xffffffffu, s,  o);
        s2 += __shfl_xor_sync(0xffffffffu, s2, o);
    }
    float mu = s * (1.f / Dn);
    float var = s2 * (1.f / Dn) - mu * mu;
    float rstd = rsqrtf(var + EPSf);
#pragma unroll
    for (int e = 0; e < 6; e++) {
        int idx = lane + 32 * e;
        float o_ = ok ? fmaf((v[e] - mu) * rstd, g2[idx], b2[idx]) : v[e];
        xn_out[(long long)row * Dn + idx] = o_;
    }
}

// ---------------------------------------------------------------------------
// Batched FFMA2 GEMM: C[z] = A[z] @ W[z] + bias[z], EPI=1: exact GELU.
// Tile 128x64, BK=16, 256 threads, microtile 4 row-pairs x 4 cols.
// A pairs load directly from smem (broadcast); B scalar + pk2 dup in regs.
// Coalesced epilogue via smem staging.
// ---------------------------------------------------------------------------
struct GemmBatch {
    const float* A[6];
    const float* W[6];
    const float* bias[6];
    float* C[6];
};

template <int EPI>
__global__ __launch_bounds__(256) void gemm_f2_kernel(
    GemmBatch g, int M, int N, int K)
{
    __shared__ __align__(16) float sm[9216];   // 36 KB (epilogue reuse: 128x72)
    float (*As)[16][136] = (float(*)[16][136])sm;            // [buf][k][m]
    float (*Bs)[16][68]  = (float(*)[16][68])(sm + 4352);    // [buf][k][n]

    const int z = blockIdx.z;
    const float* __restrict__ A = g.A[z];
    const float* __restrict__ W = g.W[z];
    const float* __restrict__ bias = g.bias[z];
    float* __restrict__ C = g.C[z];

    const int tid = threadIdx.x;
    const int tx = tid & 15, ty = tid >> 4;
    const int bm = blockIdx.x * 128, bn = blockIdx.y * 64;

    const int arow = tid >> 1, ak = (tid & 1) * 8;   // A loader
    const int bk   = tid >> 4, bc = (tid & 15) * 4;  // B loader

    const float* gA = A + (long long)(bm + arow) * K + ak;
    const float* gB = W + (long long)bk * N + bn + bc;

    float ar[8];
    float4 bstage;

    // prologue: tile 0 -> buf 0
    *(float4*)&ar[0] = *(const float4*)(gA);
    *(float4*)&ar[4] = *(const float4*)(gA + 4);
    bstage = *(const float4*)(gB);
#pragma unroll
    for (int c = 0; c < 8; c++) As[0][ak + c][arow] = ar[c];
    *(float4*)&Bs[0][bk][bc] = bstage;

    ull acc[4][4];
#pragma unroll
    for (int r = 0; r < 4; r++)
#pragma unroll
        for (int c = 0; c < 4; c++) acc[r][c] = 0ull;

    const int T = K >> 4;
    for (int t = 0; t < T; t++) {
        __syncthreads();
        const int buf = t & 1;
        if (t + 1 < T) {
            *(float4*)&ar[0] = *(const float4*)(gA + (t + 1) * 16);
            *(float4*)&ar[4] = *(const float4*)(gA + (t + 1) * 16 + 4);
            bstage = *(const float4*)(gB + (long long)(t + 1) * 16 * N);
        }
#pragma unroll
        for (int k = 0; k < 16; k++) {
            const ull* ap = (const ull*)&As[buf][k][ty * 8];   // 4 row-pairs (broadcast)
            ull a0 = ap[0], a1 = ap[1], a2 = ap[2], a3 = ap[3];
            float4 bq = *(const float4*)&Bs[buf][k][tx * 4];
            ull b0 = pk2(bq.x, bq.x), b1 = pk2(bq.y, bq.y);
            ull b2 = pk2(bq.z, bq.z), b3 = pk2(bq.w, bq.w);
            acc[0][0] = ffma2(a0, b0, acc[0][0]); acc[0][1] = ffma2(a0, b1, acc[0][1]);
            acc[0][2] = ffma2(a0, b2, acc[0][2]); acc[0][3] = ffma2(a0, b3, acc[0][3]);
            acc[1][0] = ffma2(a1, b0, acc[1][0]); acc[1][1] = ffma2(a1, b1, acc[1][1]);
            acc[1][2] = ffma2(a1, b2, acc[1][2]); acc[1][3] = ffma2(a1, b3, acc[1][3]);
            acc[2][0] = ffma2(a2, b0, acc[2][0]); acc[2][1] = ffma2(a2, b1, acc[2][1]);
            acc[2][2] = ffma2(a2, b2, acc[2][2]); acc[2][3] = ffma2(a2, b3, acc[2][3]);
            acc[3][0] = ffma2(a3, b0, acc[3][0]); acc[3][1] = ffma2(a3, b1, acc[3][1]);
            acc[3][2] = ffma2(a3, b2, acc[3][2]); acc[3][3] = ffma2(a3, b3, acc[3][3]);
        }
        if (t + 1 < T) {
            const int nb = buf ^ 1;
#pragma unroll
            for (int c = 0; c < 8; c++) As[nb][ak + c][arow] = ar[c];
            *(float4*)&Bs[nb][bk][bc] = bstage;
        }
    }

    __syncthreads();   // reuse sm as epilogue stage [128][72]
    float4 b4 = *(const float4*)(bias + bn + tx * 4);
#pragma unroll
    for (int c = 0; c < 4; c++) {
        float bv = (c == 0) ? b4.x : (c == 1) ? b4.y : (c == 2) ? b4.z : b4.w;
#pragma unroll
        for (int r = 0; r < 4; r++) {
            float e0, e1;
            upk2(acc[r][c], e0, e1);
            e0 += bv; e1 += bv;
            if (EPI == 1) { e0 *= normcdff(e0); e1 *= normcdff(e1); }
            sm[(ty * 8 + 2 * r)     * 72 + tx * 4 + c] = e0;
            sm[(ty * 8 + 2 * r + 1) * 72 + tx * 4 + c] = e1;
        }
    }
    __syncthreads();
    const int mrow = tid >> 1, half = (tid & 1) * 32;
#pragma unroll
    for (int q = 0; q < 8; q++) {
        float4 v = *(const float4*)&sm[mrow * 72 + half + q * 4];
        *(float4*)(C + (long long)(bm + mrow) * N + bn + half + q * 4) = v;
    }
}

// ---------------------------------------------------------------------------
// Flash attention (round-3 inner math), batched over direction (blockIdx.z).
// ---------------------------------------------------------------------------
struct FlashArgs {
    const float* Q[2];
    const float* K[2];
    const float* V[2];
    const unsigned int* vq[2];
    const unsigned int* vk[2];
    float* ctx[2];
};

__global__ __launch_bounds__(256) void flash_kernel(FlashArgs fa)
{
    __shared__ __align__(16) float Qs[32][68];   // [d][m], Q pre-scaled
    __shared__ __align__(16) float Ks[32][68];   // [d][n]
    __shared__ __align__(16) float Vs[64][34];   // [j][d]
    __shared__ __align__(16) float Ps[64][68];   // [m][j]
    __shared__ unsigned char vqs[64];
    __shared__ unsigned char vks[64];

    const int tid = threadIdx.x;
    const int tx = tid & 15, ty = tid >> 4;
    const int qt = blockIdx.x;
    const int bh = blockIdx.y;
    const int z  = blockIdx.z;
    const int b = bh / Hn, h = bh % Hn;

    const float* Qb = fa.Q[z] + (long long)b * Ln * Dn + h * DKn;
    const float* Kb = fa.K[z] + (long long)b * Ln * Dn + h * DKn;
    const float* Vb = fa.V[z] + (long long)b * Ln * Dn + h * DKn;
    const unsigned int* vq = fa.vq[z];
    const unsigned int* vk = fa.vk[z];
    float* ctx = fa.ctx[z];

    const int ld = tid & 31, lr = tid >> 5;

#pragma unroll
    for (int i = 0; i < 8; i++) {
        int r = lr + i * 8;
        Qs[ld][r] = Qb[(long long)(qt * 64 + r) * Dn + ld] * SCALE;
        Ks[ld][r] = Kb[(long long)r * Dn + ld];
        Vs[r][ld] = Vb[(long long)r * Dn + ld];
    }
    if (tid < 64)       vqs[tid]      = (vq[b * Ln + qt * 64 + tid] != 0u) ? 1 : 0;
    else if (tid < 128) vks[tid - 64] = (vk[b * Ln + tid - 64]      != 0u) ? 1 : 0;
    __syncthreads();

    ull   o2[4]   = {0ull, 0ull, 0ull, 0ull};
    float mrow[4] = {-INFINITY, -INFINITY, -INFINITY, -INFINITY};
    float lrow[4] = {0.f, 0.f, 0.f, 0.f};

    float kreg[8], vreg[8];
    unsigned int vkr = 0u;

    for (int t = 0; t < 8; t++) {
        // ---- S = (scaled Q) K^T ----
        ull s01[4] = {0ull, 0ull, 0ull, 0ull};
        ull s23[4] = {0ull, 0ull, 0ull, 0ull};
#pragma unroll
        for (int k = 0; k < 32; k++) {
            float4 aq = *(const float4*)&Qs[k][ty * 4];
            const ull* bp = (const ull*)&Ks[k][tx * 4];
            ull b01 = bp[0], b23 = bp[1];
            ull a;
            a = pk2(aq.x, aq.x); s01[0] = ffma2(a, b01, s01[0]); s23[0] = ffma2(a, b23, s23[0]);
            a = pk2(aq.y, aq.y); s01[1] = ffma2(a, b01, s01[1]); s23[1] = ffma2(a, b23, s23[1]);
            a = pk2(aq.z, aq.z); s01[2] = ffma2(a, b01, s01[2]); s23[2] = ffma2(a, b23, s23[2]);
            a = pk2(aq.w, aq.w); s01[3] = ffma2(a, b01, s01[3]); s23[3] = ffma2(a, b23, s23[3]);
        }

        // ---- prefetch next K/V tile ----
        if (t < 7) {
#pragma unroll
            for (int i = 0; i < 8; i++) {
                int r = (t + 1) * 64 + lr + i * 8;
                kreg[i] = Kb[(long long)r * Dn + ld];
                vreg[i] = Vb[(long long)r * Dn + ld];
            }
            if (tid < 64) vkr = vk[b * Ln + (t + 1) * 64 + tid];
        }

        // ---- mask + online softmax ----
        float s[4][4];
#pragma unroll
        for (int i = 0; i < 4; i++) {
            upk2(s01[i], s[i][0], s[i][1]);
            upk2(s23[i], s[i][2], s[i][3]);
            bool qok = vqs[ty * 4 + i] != 0;
#pragma unroll
            for (int j = 0; j < 4; j++)
                if (!(qok && vks[tx * 4 + j])) s[i][j] = -1e9f;
        }
#pragma unroll
        for (int i = 0; i < 4; i++) {
            float tm = fmaxf(fmaxf(s[i][0], s[i][1]), fmaxf(s[i][2], s[i][3]));
#pragma unroll
            for (int o = 8; o > 0; o >>= 1)
                tm = fmaxf(tm, __shfl_xor_sync(0xffffffffu, tm, o));
            float nm = fmaxf(mrow[i], tm);
            float p0 = __expf(s[i][0] - nm);
            float p1 = __expf(s[i][1] - nm);
            float p2 = __expf(s[i][2] - nm);
            float p3 = __expf(s[i][3] - nm);
            float ts = (p0 + p1) + (p2 + p3);
#pragma unroll
            for (int o = 8; o > 0; o >>= 1)
                ts += __shfl_xor_sync(0xffffffffu, ts, o);
            float fac = __expf(mrow[i] - nm);
            lrow[i] = lrow[i] * fac + ts;
            mrow[i] = nm;
            o2[i] = fmul2(o2[i], pk2(fac, fac));
            *(float4*)&Ps[ty * 4 + i][tx * 4] = make_float4(p0, p1, p2, p3);
        }
        __syncthreads();

        // ---- O += P @ V ----
#pragma unroll 4
        for (int j = 0; j < 64; j++) {
            ull v2 = *(const ull*)&Vs[j][tx * 2];
#pragma unroll
            for (int i = 0; i < 4; i++) {
                float p = Ps[ty * 4 + i][j];
                o2[i] = ffma2(pk2(p, p), v2, o2[i]);
            }
        }
        __syncthreads();

        if (t < 7) {
#pragma unroll
            for (int i = 0; i < 8; i++) {
                int r = lr + i * 8;
                Ks[ld][r] = kreg[i];
                Vs[r][ld] = vreg[i];
            }
            if (tid < 64) vks[tid] = (vkr != 0u) ? 1 : 0;
            __syncthreads();
        }
    }

#pragma unroll
    for (int i = 0; i < 4; i++) {
        float o0, o1;
        upk2(o2[i], o0, o1);
        float inv = 1.f / lrow[i];
        long long row = (long long)b * Ln + qt * 64 + ty * 4 + i;
        *(float2*)(ctx + row * Dn + h * DKn + tx * 2) = make_float2(o0 * inv, o1 * inv);
    }
}

// ---------------------------------------------------------------------------
// Host launcher
// ---------------------------------------------------------------------------
extern "C" void kernel_launch(void* const* d_in, const int* in_sizes, int n_in,
                              void* d_out, int out_size)
{
    const float* x_a = (const float*)d_in[0];
    const float* x_b = (const float*)d_in[1];
    const unsigned int* valid_a = (const unsigned int*)d_in[2];
    const unsigned int* valid_b = (const unsigned int*)d_in[3];
    const float* ln_a_g  = (const float*)d_in[4];
    const float* ln_a_b  = (const float*)d_in[5];
    const float* ln_b_g  = (const float*)d_in[6];
    const float* ln_b_b  = (const float*)d_in[7];
    const float* ln_oa_g = (const float*)d_in[8];
    const float* ln_oa_b = (const float*)d_in[9];
    const float* ln_ob_g = (const float*)d_in[10];
    const float* ln_ob_b = (const float*)d_in[11];
    const float* wq = (const float*)d_in[12];
    const float* bq = (const float*)d_in[13];
    const float* wk = (const float*)d_in[14];
    const float* bk = (const float*)d_in[15];
    const float* wv = (const float*)d_in[16];
    const float* bv = (const float*)d_in[17];
    const float* wo = (const float*)d_in[18];
    const float* bo = (const float*)d_in[19];
    const float* fln_g  = (const float*)d_in[20];
    const float* fln_b  = (const float*)d_in[21];
    const float* flno_g = (const float*)d_in[22];
    const float* flno_b = (const float*)d_in[23];
    const float* w1 = (const float*)d_in[24];
    const float* b1 = (const float*)d_in[25];
    const float* w2 = (const float*)d_in[26];
    const float* b2 = (const float*)d_in[27];

    float* ws = nullptr;
    cudaGetSymbolAddress((void**)&ws, g_ws);

    float* aln  = ws + 0 * BLD;
    float* bln  = ws + 1 * BLD;
    float* Qa   = ws + 2 * BLD;
    float* Ka   = ws + 3 * BLD;
    float* Va   = ws + 4 * BLD;
    float* Qb   = ws + 5 * BLD;
    float* Kb   = ws + 6 * BLD;
    float* Vb   = ws + 7 * BLD;
    float* ctxa = ws + 8 * BLD;
    float* ctxb = ws + 9 * BLD;
    float* tmpa = ws + 10 * BLD;
    float* tmpb = ws + 11 * BLD;
    float* oa   = ws + 12 * BLD;
    float* ob   = ws + 13 * BLD;
    float* xna  = ws + 14 * BLD;
    float* xnb  = ws + 15 * BLD;
    float* yba  = ws + 16 * BLD;
    float* ybb  = ws + 17 * BLD;
    float* hida = ws + 18 * BLD;
    float* hidb = hida + SZ_HID;

    float* out_a = (float*)d_out;
    float* out_b = (float*)d_out + BLD;

    dim3 blk(256);
    dim3 gLN(ROWS / 8);

    // 1. pre-attention masked LN
    mln_kernel<<<gLN, blk>>>(x_a, nullptr, valid_a, ln_a_g, ln_a_b, aln);
    mln_kernel<<<gLN, blk>>>(x_b, nullptr, valid_b, ln_b_g, ln_b_b, bln);

    // 2. six projections, one batched launch
    {
        GemmBatch g;
        g.A[0] = aln; g.A[1] = aln; g.A[2] = aln;
        g.A[3] = bln; g.A[4] = bln; g.A[5] = bln;
        g.W[0] = wq;  g.W[1] = wk;  g.W[2] = wv;
        g.W[3] = wq;  g.W[4] = wk;  g.W[5] = wv;
        g.bias[0] = bq; g.bias[1] = bk; g.bias[2] = bv;
        g.bias[3] = bq; g.bias[4] = bk; g.bias[5] = bv;
        g.C[0] = Qa; g.C[1] = Ka; g.C[2] = Va;
        g.C[3] = Qb; g.C[4] = Kb; g.C[5] = Vb;
        dim3 grid(ROWS / 128, Dn / 64, 6);
        gemm_f2_kernel<0><<<grid, blk>>>(g, ROWS, Dn, Dn);
    }

    // 3. flash attention, both directions in one launch
    {
        FlashArgs fa;
        fa.Q[0] = Qa; fa.K[0] = Kb; fa.V[0] = Vb; fa.vq[0] = valid_a; fa.vk[0] = valid_b; fa.ctx[0] = ctxa;
        fa.Q[1] = Qb; fa.K[1] = Ka; fa.V[1] = Va; fa.vq[1] = valid_b; fa.vk[1] = valid_a; fa.ctx[1] = ctxb;
        dim3 grid(Ln / 64, Bn * Hn, 2);
        flash_kernel<<<grid, blk>>>(fa);
    }

    // 4. output projection (batched) + fused residual-LN + pre-FFN LN
    {
        GemmBatch g = {};
        g.A[0] = ctxa; g.A[1] = ctxb;
        g.W[0] = wo;   g.W[1] = wo;
        g.bias[0] = bo; g.bias[1] = bo;
        g.C[0] = tmpa; g.C[1] = tmpb;
        dim3 grid(ROWS / 128, Dn / 64, 2);
        gemm_f2_kernel<0><<<grid, blk>>>(g, ROWS, Dn, Dn);
    }
    mln2_kernel<<<gLN, blk>>>(tmpa, x_a, valid_a, ln_oa_g, ln_oa_b, fln_g, fln_b, oa, xna);
    mln2_kernel<<<gLN, blk>>>(tmpb, x_b, valid_b, ln_ob_g, ln_ob_b, fln_g, fln_b, ob, xnb);

    // 5. FFN w1 (GELU) batched
    {
        GemmBatch g = {};
        g.A[0] = xna; g.A[1] = xnb;
        g.W[0] = w1;  g.W[1] = w1;
        g.bias[0] = b1; g.bias[1] = b1;
        g.C[0] = hida; g.C[1] = hidb;
        dim3 grid(ROWS / 128, HIDn / 64, 2);
        gemm_f2_kernel<1><<<grid, blk>>>(g, ROWS, HIDn, Dn);
    }
    // 6. FFN w2 batched
    {
        GemmBatch g = {};
        g.A[0] = hida; g.A[1] = hidb;
        g.W[0] = w2;   g.W[1] = w2;
        g.bias[0] = b2; g.bias[1] = b2;
        g.C[0] = yba;  g.C[1] = ybb;
        dim3 grid(ROWS / 128, Dn / 64, 2);
        gemm_f2_kernel<0><<<grid, blk>>>(g, ROWS, Dn, HIDn);
    }
    // 7. final masked LN (+residual)
    mln_kernel<<<gLN, blk>>>(yba, oa, valid_a, flno_g, flno_b, out_a);
    mln_kernel<<<gLN, blk>>>(ybb, ob, valid_b, flno_g, flno_b, out_b);
}

// round 7
// speedup vs baseline: 1.7071x; 1.1380x over previous
#include <cuda_runtime.h>
#include <cuda_bf16.h>
#include <math.h>
#include <cstdint>

// ---------------------------------------------------------------------------
// Problem constants
// ---------------------------------------------------------------------------
static constexpr int Bn   = 48;
static constexpr int Ln   = 512;
static constexpr int Dn   = 192;
static constexpr int Hn   = 6;
static constexpr int DKn  = 32;
static constexpr int HIDn = 768;
static constexpr int ROWS = Bn * Ln;                         // 24576
static constexpr long long BLD = (long long)ROWS * Dn;       // 4,718,592
static constexpr float SCALE = 0.17677669529663689f;         // 1/sqrt(32)
static constexpr float EPSf  = 1e-5f;

static constexpr int K3D = 3 * Dn;      // 576  (split-K for K=192)
static constexpr int K3H = 3 * HIDn;    // 2304 (split-K for K=768)
static constexpr long long SZ_S3  = (long long)ROWS * K3D;
static constexpr long long SZ_H3  = (long long)ROWS * K3H;

// ---------------------------------------------------------------------------
// Static scratch
// ---------------------------------------------------------------------------
__device__ float g_ws[12 * BLD];

static constexpr long long OFF_ALN  = 0;
static constexpr long long OFF_BLN  = OFF_ALN  + SZ_S3;
static constexpr long long OFF_CTXA = OFF_BLN  + SZ_S3;
static constexpr long long OFF_CTXB = OFF_CTXA + SZ_S3;
static constexpr long long OFF_XNA  = OFF_CTXB + SZ_S3;
static constexpr long long OFF_XNB  = OFF_XNA  + SZ_S3;
static constexpr long long OFF_HIDA = OFF_XNB  + SZ_S3;
static constexpr long long OFF_HIDB = OFF_HIDA + SZ_H3;
static constexpr long long OFF_WQ   = OFF_HIDB + SZ_H3;
static constexpr long long SZ_WSML  = (long long)Dn * K3D;
static constexpr long long OFF_WK   = OFF_WQ + SZ_WSML;
static constexpr long long OFF_WV   = OFF_WK + SZ_WSML;
static constexpr long long OFF_WO   = OFF_WV + SZ_WSML;
static constexpr long long OFF_W1   = OFF_WO + SZ_WSML;
static constexpr long long SZ_W1S   = (long long)HIDn * K3D;
static constexpr long long OFF_W2   = OFF_W1 + SZ_W1S;
static constexpr long long SZ_W2S   = (long long)Dn * K3H;
static constexpr long long WSB_TOT  = OFF_W2 + SZ_W2S;
__device__ __nv_bfloat16 g_wsb[WSB_TOT];

// ---------------------------------------------------------------------------
// f32x2 packed helpers (SIMT flash path)
// ---------------------------------------------------------------------------
typedef unsigned long long ull;
__device__ __forceinline__ ull pk2(float lo, float hi) {
    ull r; asm("mov.b64 %0, {%1,%2};" : "=l"(r) : "f"(lo), "f"(hi)); return r;
}
__device__ __forceinline__ void upk2(ull v, float& lo, float& hi) {
    asm("mov.b64 {%0,%1}, %2;" : "=f"(lo), "=f"(hi) : "l"(v));
}
__device__ __forceinline__ ull ffma2(ull a, ull b, ull c) {
    ull d; asm("fma.rn.f32x2 %0, %1, %2, %3;" : "=l"(d) : "l"(a), "l"(b), "l"(c)); return d;
}
__device__ __forceinline__ ull fmul2(ull a, ull b) {
    ull d; asm("mul.rn.f32x2 %0, %1, %2;" : "=l"(d) : "l"(a), "l"(b)); return d;
}

// ---------------------------------------------------------------------------
// mma.sync helpers (family-generic PTX: works on base sm_103 target)
// ---------------------------------------------------------------------------
__device__ __forceinline__ uint32_t smem_to_u32(const void* p) {
    uint32_t a;
    asm("{ .reg .u64 t; cvta.to.shared.u64 t, %1; cvt.u32.u64 %0, t; }" : "=r"(a) : "l"(p));
    return a;
}
__device__ __forceinline__ void ldsm_x4(uint32_t& r0, uint32_t& r1, uint32_t& r2, uint32_t& r3,
                                        uint32_t addr) {
    asm volatile("ldmatrix.sync.aligned.m8n8.x4.shared.b16 {%0,%1,%2,%3}, [%4];"
                 : "=r"(r0), "=r"(r1), "=r"(r2), "=r"(r3) : "r"(addr));
}
__device__ __forceinline__ void mma_bf16(float& c0, float& c1, float& c2, float& c3,
                                         uint32_t a0, uint32_t a1, uint32_t a2, uint32_t a3,
                                         uint32_t b0, uint32_t b1) {
    asm volatile("mma.sync.aligned.m16n8k16.row.col.f32.bf16.bf16.f32 "
                 "{%0,%1,%2,%3}, {%4,%5,%6,%7}, {%8,%9}, {%0,%1,%2,%3};"
                 : "+f"(c0), "+f"(c1), "+f"(c2), "+f"(c3)
                 : "r"(a0), "r"(a1), "r"(a2), "r"(a3), "r"(b0), "r"(b1));
}

// ---------------------------------------------------------------------------
// split write helper: x -> (hi, lo) bf16 with x ~= hi + lo
// ---------------------------------------------------------------------------
__device__ __forceinline__ void bf16_split(float x, __nv_bfloat16& hi, __nv_bfloat16& lo) {
    hi = __float2bfloat16(x);
    lo = __float2bfloat16(x - __bfloat162float(hi));
}

// ---------------------------------------------------------------------------
// Weight split/transpose: W[K,N] fp32 -> out[N, 3K] bf16 = [hi | lo | hi]
// ---------------------------------------------------------------------------
__global__ void wsplit_kernel(const float* __restrict__ W, __nv_bfloat16* __restrict__ out,
                              int K, int N)
{
    int idx = blockIdx.x * 256 + threadIdx.x;
    if (idx >= K * N) return;
    int k = idx / N, n = idx % N;
    __nv_bfloat16 hi, lo;
    bf16_split(W[idx], hi, lo);
    long long base = (long long)n * (3 * K) + k;
    out[base]         = hi;
    out[base + K]     = lo;
    out[base + 2 * K] = hi;
}

// ---------------------------------------------------------------------------
// Masked LayerNorm. One warp per row. fp32 out (outs null) or split bf16
// [hi | hi | lo], row stride 3*Dn.
// ---------------------------------------------------------------------------
__device__ __forceinline__ void mln_core(const float* xr, const float* rr, bool ok,
                                         const float* gamma, const float* beta,
                                         int lane, float* v)
{
    float s = 0.f;
#pragma unroll
    for (int e = 0; e < 6; e++) {
        int idx = lane + 32 * e;
        float t = xr[idx];
        if (rr) t += rr[idx];
        v[e] = t; s += t;
    }
    float s2 = 0.f;
#pragma unroll
    for (int e = 0; e < 6; e++) s2 += v[e] * v[e];
#pragma unroll
    for (int o = 16; o > 0; o >>= 1) {
        s  += __shfl_xor_sync(0xffffffffu, s,  o);
        s2 += __shfl_xor_sync(0xffffffffu, s2, o);
    }
    float mu = s * (1.f / Dn), var = s2 * (1.f / Dn) - mu * mu;
    float rstd = rsqrtf(var + EPSf);
#pragma unroll
    for (int e = 0; e < 6; e++) {
        int idx = lane + 32 * e;
        v[e] = ok ? fmaf((v[e] - mu) * rstd, gamma[idx], beta[idx]) : v[e];
    }
}

__global__ void mln_kernel(const float* __restrict__ x, const float* __restrict__ res,
                           const unsigned int* __restrict__ valid,
                           const float* __restrict__ gamma, const float* __restrict__ beta,
                           float* __restrict__ outf, __nv_bfloat16* __restrict__ outs)
{
    int warp = threadIdx.x >> 5, lane = threadIdx.x & 31;
    int row  = blockIdx.x * 8 + warp;
    float v[6];
    mln_core(x + (long long)row * Dn, res ? res + (long long)row * Dn : nullptr,
             valid[row] != 0u, gamma, beta, lane, v);
    if (outs) {
        long long rb = (long long)row * K3D;
#pragma unroll
        for (int e = 0; e < 6; e++) {
            int idx = lane + 32 * e;
            __nv_bfloat16 hi, lo; bf16_split(v[e], hi, lo);
            outs[rb + idx] = hi; outs[rb + Dn + idx] = hi; outs[rb + 2 * Dn + idx] = lo;
        }
    } else {
#pragma unroll
        for (int e = 0; e < 6; e++)
            outf[(long long)row * Dn + lane + 32 * e] = v[e];
    }
}

// fused: o = mln(x+res) (fp32); xn = mln(o) (split bf16)
__global__ void mln2_kernel(const float* __restrict__ x, const float* __restrict__ res,
                            const unsigned int* __restrict__ valid,
                            const float* __restrict__ g1, const float* __restrict__ b1,
                            const float* __restrict__ g2, const float* __restrict__ b2,
                            float* __restrict__ o_out, __nv_bfloat16* __restrict__ xn_out)
{
    int warp = threadIdx.x >> 5, lane = threadIdx.x & 31;
    int row  = blockIdx.x * 8 + warp;
    bool ok = valid[row] != 0u;
    float v[6];
    mln_core(x + (long long)row * Dn, res + (long long)row * Dn, ok, g1, b1, lane, v);
#pragma unroll
    for (int e = 0; e < 6; e++)
        o_out[(long long)row * Dn + lane + 32 * e] = v[e];
    float s = 0.f, s2 = 0.f;
#pragma unroll
    for (int e = 0; e < 6; e++) { s += v[e]; s2 += v[e] * v[e]; }
#pragma unroll
    for (int o = 16; o > 0; o >>= 1) {
        s  += __shfl_xor_sync(0xffffffffu, s,  o);
        s2 += __shfl_xor_sync(0xffffffffu, s2, o);
    }
    float mu = s * (1.f / Dn), var = s2 * (1.f / Dn) - mu * mu;
    float rstd = rsqrtf(var + EPSf);
    long long rb = (long long)row * K3D;
#pragma unroll
    for (int e = 0; e < 6; e++) {
        int idx = lane + 32 * e;
        float o_ = ok ? fmaf((v[e] - mu) * rstd, g2[idx], b2[idx]) : v[e];
        __nv_bfloat16 hi, lo; bf16_split(o_, hi, lo);
        xn_out[rb + idx] = hi; xn_out[rb + Dn + idx] = hi; xn_out[rb + 2 * Dn + idx] = lo;
    }
}

// ---------------------------------------------------------------------------
// Warp-MMA GEMM: C[m,n] = sum_k A'[m,k] B'[n,k] + bias[n]
// A' [M,K3] bf16 K-major, B' [Nt,K3] bf16 K-major.
// Tile 128x64, BK=32, 256 threads = 8 warps (4m x 2n), warp tile 32x32.
// mma.sync.m16n8k16 bf16->f32. Double-buffered smem, register prefetch.
// EPI 0: fp32 out. EPI 1: GELU + split-bf16 out [hi|hi|lo] (row ld 3*Nt).
// ---------------------------------------------------------------------------
struct TcBatch {
    const __nv_bfloat16* A[6];
    const __nv_bfloat16* B[6];
    const float* bias[6];
    void* C[6];
};

template <int EPI>
__global__ __launch_bounds__(256) void mma_gemm_kernel(TcBatch tb, int K3, int Nt)
{
    __shared__ __align__(16) __nv_bfloat16 As[2][128][40];   // 20 KB
    __shared__ __align__(16) __nv_bfloat16 Bs[2][64][40];    // 10 KB

    const int tid  = threadIdx.x;
    const int lane = tid & 31, wid = tid >> 5;
    const int wm = wid & 3, wn = wid >> 2;
    const int z  = blockIdx.z;
    const int bm = blockIdx.x * 128, bn = blockIdx.y * 64;

    const __nv_bfloat16* __restrict__ Ag = tb.A[z];
    const __nv_bfloat16* __restrict__ Bg = tb.B[z];

    // global loaders: 16B per thread
    const int u = tid & 3;        // 16B unit within 64B k-row
    const int r = tid >> 2;       // 0..63
    const __nv_bfloat16* gA0 = Ag + (long long)(bm + r)      * K3 + u * 8;
    const __nv_bfloat16* gA1 = Ag + (long long)(bm + r + 64) * K3 + u * 8;
    const __nv_bfloat16* gB0 = Bg + (long long)(bn + r)      * K3 + u * 8;

    uint4 pa0 = *(const uint4*)gA0;
    uint4 pa1 = *(const uint4*)gA1;
    uint4 pb0 = *(const uint4*)gB0;
    *(uint4*)&As[0][r][u * 8]      = pa0;
    *(uint4*)&As[0][r + 64][u * 8] = pa1;
    *(uint4*)&Bs[0][r][u * 8]      = pb0;

    // ldmatrix per-thread row/col offsets
    const int j = lane >> 3, i8 = lane & 7;
    const int aRow = (j & 1) * 8 + i8;   // within 16-row frag
    const int aCol = (j >> 1) * 8;       // k offset within 16
    const int bRow = (j >> 1) * 8 + i8;  // within 16-n group
    const int bCol = (j & 1) * 8;        // k offset within 16

    const uint32_t AsB = smem_to_u32(&As[0][0][0]);
    const uint32_t BsB = smem_to_u32(&Bs[0][0][0]);

    float acc[2][4][4];
#pragma unroll
    for (int f = 0; f < 2; f++)
#pragma unroll
        for (int g = 0; g < 4; g++)
#pragma unroll
            for (int e = 0; e < 4; e++) acc[f][g][e] = 0.f;

    const int T = K3 >> 5;
    for (int t = 0; t < T; t++) {
        __syncthreads();
        const int buf = t & 1;
        if (t + 1 < T) {
            pa0 = *(const uint4*)(gA0 + (t + 1) * 32);
            pa1 = *(const uint4*)(gA1 + (t + 1) * 32);
            pb0 = *(const uint4*)(gB0 + (t + 1) * 32);
        }
        const uint32_t aBuf = AsB + buf * (128 * 40 * 2);
        const uint32_t bBuf = BsB + buf * (64 * 40 * 2);
#pragma unroll
        for (int ks = 0; ks < 2; ks++) {
            const int k0 = ks * 16;
            uint32_t a[2][4];
#pragma unroll
            for (int f = 0; f < 2; f++) {
                uint32_t ad = aBuf + (uint32_t)(((wm * 32 + f * 16 + aRow) * 40 + k0 + aCol) * 2);
                ldsm_x4(a[f][0], a[f][1], a[f][2], a[f][3], ad);
            }
            uint32_t b[4][2];
#pragma unroll
            for (int g2 = 0; g2 < 2; g2++) {
                uint32_t bd = bBuf + (uint32_t)(((wn * 32 + g2 * 16 + bRow) * 40 + k0 + bCol) * 2);
                uint32_t r0, r1, r2, r3;
                ldsm_x4(r0, r1, r2, r3, bd);
                b[g2 * 2][0] = r0; b[g2 * 2][1] = r1;
                b[g2 * 2 + 1][0] = r2; b[g2 * 2 + 1][1] = r3;
            }
#pragma unroll
            for (int f = 0; f < 2; f++)
#pragma unroll
                for (int g = 0; g < 4; g++)
                    mma_bf16(acc[f][g][0], acc[f][g][1], acc[f][g][2], acc[f][g][3],
                             a[f][0], a[f][1], a[f][2], a[f][3], b[g][0], b[g][1]);
        }
        if (t + 1 < T) {
            const int nb = buf ^ 1;
            *(uint4*)&As[nb][r][u * 8]      = pa0;
            *(uint4*)&As[nb][r + 64][u * 8] = pa1;
            *(uint4*)&Bs[nb][r][u * 8]      = pb0;
        }
    }

    // epilogue
    const float* __restrict__ bias = tb.bias[z];
    const int mr = lane >> 2, nc = (lane & 3) * 2;
#pragma unroll
    for (int f = 0; f < 2; f++) {
#pragma unroll
        for (int g = 0; g < 4; g++) {
            const int m0 = bm + wm * 32 + f * 16 + mr;
            const int n0 = bn + wn * 32 + g * 8 + nc;
            const float bv0 = __ldg(bias + n0), bv1 = __ldg(bias + n0 + 1);
            float v00 = acc[f][g][0] + bv0, v01 = acc[f][g][1] + bv1;
            float v10 = acc[f][g][2] + bv0, v11 = acc[f][g][3] + bv1;
            if (EPI == 0) {
                float* C = (float*)tb.C[z];
                *(float2*)(C + (long long)m0 * Nt + n0)       = make_float2(v00, v01);
                *(float2*)(C + (long long)(m0 + 8) * Nt + n0) = make_float2(v10, v11);
            } else {
                v00 *= normcdff(v00); v01 *= normcdff(v01);
                v10 *= normcdff(v10); v11 *= normcdff(v11);
                __nv_bfloat16* C = (__nv_bfloat16*)tb.C[z];
                __nv_bfloat16 h0, l0, h1, l1;
                long long base0 = (long long)m0 * (3 * Nt) + n0;
                bf16_split(v00, h0, l0); bf16_split(v01, h1, l1);
                { __nv_bfloat162 hp; hp.x = h0; hp.y = h1;
                  __nv_bfloat162 lp; lp.x = l0; lp.y = l1;
                  *(__nv_bfloat162*)(C + base0)          = hp;
                  *(__nv_bfloat162*)(C + base0 + Nt)     = hp;
                  *(__nv_bfloat162*)(C + base0 + 2 * Nt) = lp; }
                long long base1 = (long long)(m0 + 8) * (3 * Nt) + n0;
                bf16_split(v10, h0, l0); bf16_split(v11, h1, l1);
                { __nv_bfloat162 hp; hp.x = h0; hp.y = h1;
                  __nv_bfloat162 lp; lp.x = l0; lp.y = l1;
                  *(__nv_bfloat162*)(C + base1)          = hp;
                  *(__nv_bfloat162*)(C + base1 + Nt)     = hp;
                  *(__nv_bfloat162*)(C + base1 + 2 * Nt) = lp; }
            }
        }
    }
}

// ---------------------------------------------------------------------------
// Flash attention (SIMT, R5 math), ctx emitted as split bf16 [hi|hi|lo].
// ---------------------------------------------------------------------------
struct FlashArgs {
    const float* Q[2];
    const float* K[2];
    const float* V[2];
    const unsigned int* vq[2];
    const unsigned int* vk[2];
    __nv_bfloat16* ctx[2];
};

__global__ __launch_bounds__(256) void flash_kernel(FlashArgs fa)
{
    __shared__ __align__(16) float Qs[32][68];
    __shared__ __align__(16) float Ks[32][68];
    __shared__ __align__(16) float Vs[64][34];
    __shared__ __align__(16) float Ps[64][68];
    __shared__ unsigned char vqs[64];
    __shared__ unsigned char vks[64];

    const int tid = threadIdx.x;
    const int tx = tid & 15, ty = tid >> 4;
    const int qt = blockIdx.x;
    const int bh = blockIdx.y;
    const int z  = blockIdx.z;
    const int b = bh / Hn, h = bh % Hn;

    const float* Qb = fa.Q[z] + (long long)b * Ln * Dn + h * DKn;
    const float* Kb = fa.K[z] + (long long)b * Ln * Dn + h * DKn;
    const float* Vb = fa.V[z] + (long long)b * Ln * Dn + h * DKn;
    const unsigned int* vq = fa.vq[z];
    const unsigned int* vk = fa.vk[z];
    __nv_bfloat16* ctx = fa.ctx[z];

    const int ld = tid & 31, lr = tid >> 5;

#pragma unroll
    for (int i = 0; i < 8; i++) {
        int rr = lr + i * 8;
        Qs[ld][rr] = Qb[(long long)(qt * 64 + rr) * Dn + ld] * SCALE;
        Ks[ld][rr] = Kb[(long long)rr * Dn + ld];
        Vs[rr][ld] = Vb[(long long)rr * Dn + ld];
    }
    if (tid < 64)       vqs[tid]      = (vq[b * Ln + qt * 64 + tid] != 0u) ? 1 : 0;
    else if (tid < 128) vks[tid - 64] = (vk[b * Ln + tid - 64]      != 0u) ? 1 : 0;
    __syncthreads();

    ull   o2[4]   = {0ull, 0ull, 0ull, 0ull};
    float mrow[4] = {-INFINITY, -INFINITY, -INFINITY, -INFINITY};
    float lrow[4] = {0.f, 0.f, 0.f, 0.f};

    float kreg[8], vreg[8];
    unsigned int vkr = 0u;

    for (int t = 0; t < 8; t++) {
        ull s01[4] = {0ull, 0ull, 0ull, 0ull};
        ull s23[4] = {0ull, 0ull, 0ull, 0ull};
#pragma unroll
        for (int k = 0; k < 32; k++) {
            float4 aq = *(const float4*)&Qs[k][ty * 4];
            const ull* bp = (const ull*)&Ks[k][tx * 4];
            ull b01 = bp[0], b23 = bp[1];
            ull a;
            a = pk2(aq.x, aq.x); s01[0] = ffma2(a, b01, s01[0]); s23[0] = ffma2(a, b23, s23[0]);
            a = pk2(aq.y, aq.y); s01[1] = ffma2(a, b01, s01[1]); s23[1] = ffma2(a, b23, s23[1]);
            a = pk2(aq.z, aq.z); s01[2] = ffma2(a, b01, s01[2]); s23[2] = ffma2(a, b23, s23[2]);
            a = pk2(aq.w, aq.w); s01[3] = ffma2(a, b01, s01[3]); s23[3] = ffma2(a, b23, s23[3]);
        }

        if (t < 7) {
#pragma unroll
            for (int i = 0; i < 8; i++) {
                int rr = (t + 1) * 64 + lr + i * 8;
                kreg[i] = Kb[(long long)rr * Dn + ld];
                vreg[i] = Vb[(long long)rr * Dn + ld];
            }
            if (tid < 64) vkr = vk[b * Ln + (t + 1) * 64 + tid];
        }

        float s[4][4];
#pragma unroll
        for (int i = 0; i < 4; i++) {
            upk2(s01[i], s[i][0], s[i][1]);
            upk2(s23[i], s[i][2], s[i][3]);
            bool qok = vqs[ty * 4 + i] != 0;
#pragma unroll
            for (int jj = 0; jj < 4; jj++)
                if (!(qok && vks[tx * 4 + jj])) s[i][jj] = -1e9f;
        }
#pragma unroll
        for (int i = 0; i < 4; i++) {
            float tm = fmaxf(fmaxf(s[i][0], s[i][1]), fmaxf(s[i][2], s[i][3]));
#pragma unroll
            for (int o = 8; o > 0; o >>= 1)
                tm = fmaxf(tm, __shfl_xor_sync(0xffffffffu, tm, o));
            float nm = fmaxf(mrow[i], tm);
            float p0 = __expf(s[i][0] - nm);
            float p1 = __expf(s[i][1] - nm);
            float p2 = __expf(s[i][2] - nm);
            float p3 = __expf(s[i][3] - nm);
            float ts = (p0 + p1) + (p2 + p3);
#pragma unroll
            for (int o = 8; o > 0; o >>= 1)
                ts += __shfl_xor_sync(0xffffffffu, ts, o);
            float fac = __expf(mrow[i] - nm);
            lrow[i] = lrow[i] * fac + ts;
            mrow[i] = nm;
            o2[i] = fmul2(o2[i], pk2(fac, fac));
            *(float4*)&Ps[ty * 4 + i][tx * 4] = make_float4(p0, p1, p2, p3);
        }
        __syncthreads();

#pragma unroll 4
        for (int jj = 0; jj < 64; jj++) {
            ull v2 = *(const ull*)&Vs[jj][tx * 2];
#pragma unroll
            for (int i = 0; i < 4; i++) {
                float p = Ps[ty * 4 + i][jj];
                o2[i] = ffma2(pk2(p, p), v2, o2[i]);
            }
        }
        __syncthreads();

        if (t < 7) {
#pragma unroll
            for (int i = 0; i < 8; i++) {
                int rr = lr + i * 8;
                Ks[ld][rr] = kreg[i];
                Vs[rr][ld] = vreg[i];
            }
            if (tid < 64) vks[tid] = (vkr != 0u) ? 1 : 0;
            __syncthreads();
        }
    }

#pragma unroll
    for (int i = 0; i < 4; i++) {
        float o0, o1;
        upk2(o2[i], o0, o1);
        float inv = 1.f / lrow[i];
        o0 *= inv; o1 *= inv;
        long long row = (long long)b * Ln + qt * 64 + ty * 4 + i;
        long long base = row * K3D + h * DKn + tx * 2;
        __nv_bfloat16 h0, l0, h1, l1;
        bf16_split(o0, h0, l0);
        bf16_split(o1, h1, l1);
        __nv_bfloat162 hp; hp.x = h0; hp.y = h1;
        __nv_bfloat162 lp; lp.x = l0; lp.y = l1;
        *(__nv_bfloat162*)(ctx + base)          = hp;
        *(__nv_bfloat162*)(ctx + base + Dn)     = hp;
        *(__nv_bfloat162*)(ctx + base + 2 * Dn) = lp;
    }
}

// ---------------------------------------------------------------------------
// Host launcher
// ---------------------------------------------------------------------------
extern "C" void kernel_launch(void* const* d_in, const int* in_sizes, int n_in,
                              void* d_out, int out_size)
{
    const float* x_a = (const float*)d_in[0];
    const float* x_b = (const float*)d_in[1];
    const unsigned int* valid_a = (const unsigned int*)d_in[2];
    const unsigned int* valid_b = (const unsigned int*)d_in[3];
    const float* ln_a_g  = (const float*)d_in[4];
    const float* ln_a_b  = (const float*)d_in[5];
    const float* ln_b_g  = (const float*)d_in[6];
    const float* ln_b_b  = (const float*)d_in[7];
    const float* ln_oa_g = (const float*)d_in[8];
    const float* ln_oa_b = (const float*)d_in[9];
    const float* ln_ob_g = (const float*)d_in[10];
    const float* ln_ob_b = (const float*)d_in[11];
    const float* wq = (const float*)d_in[12];
    const float* bq = (const float*)d_in[13];
    const float* wk = (const float*)d_in[14];
    const float* bk = (const float*)d_in[15];
    const float* wv = (const float*)d_in[16];
    const float* bv = (const float*)d_in[17];
    const float* wo = (const float*)d_in[18];
    const float* bo = (const float*)d_in[19];
    const float* fln_g  = (const float*)d_in[20];
    const float* fln_b  = (const float*)d_in[21];
    const float* flno_g = (const float*)d_in[22];
    const float* flno_b = (const float*)d_in[23];
    const float* w1 = (const float*)d_in[24];
    const float* b1 = (const float*)d_in[25];
    const float* w2 = (const float*)d_in[26];
    const float* b2 = (const float*)d_in[27];

    float* ws = nullptr;
    cudaGetSymbolAddress((void**)&ws, g_ws);
    __nv_bfloat16* wb = nullptr;
    cudaGetSymbolAddress((void**)&wb, g_wsb);

    float* Qa   = ws + 0 * BLD;
    float* Ka   = ws + 1 * BLD;
    float* Va   = ws + 2 * BLD;
    float* Qb   = ws + 3 * BLD;
    float* Kb   = ws + 4 * BLD;
    float* Vb   = ws + 5 * BLD;
    float* tmpa = ws + 6 * BLD;
    float* tmpb = ws + 7 * BLD;
    float* oa   = ws + 8 * BLD;
    float* ob   = ws + 9 * BLD;
    float* yba  = ws + 10 * BLD;
    float* ybb  = ws + 11 * BLD;

    __nv_bfloat16* alnS  = wb + OFF_ALN;
    __nv_bfloat16* blnS  = wb + OFF_BLN;
    __nv_bfloat16* ctxaS = wb + OFF_CTXA;
    __nv_bfloat16* ctxbS = wb + OFF_CTXB;
    __nv_bfloat16* xnaS  = wb + OFF_XNA;
    __nv_bfloat16* xnbS  = wb + OFF_XNB;
    __nv_bfloat16* hidaS = wb + OFF_HIDA;
    __nv_bfloat16* hidbS = wb + OFF_HIDB;
    __nv_bfloat16* wqS   = wb + OFF_WQ;
    __nv_bfloat16* wkS   = wb + OFF_WK;
    __nv_bfloat16* wvS   = wb + OFF_WV;
    __nv_bfloat16* woS   = wb + OFF_WO;
    __nv_bfloat16* w1S   = wb + OFF_W1;
    __nv_bfloat16* w2S   = wb + OFF_W2;

    float* out_a = (float*)d_out;
    float* out_b = (float*)d_out + BLD;

    dim3 blk(256);
    dim3 gLN(ROWS / 8);

    // 0. weight split conversions
    {
        int nDD = Dn * Dn;
        wsplit_kernel<<<(nDD + 255) / 256, blk>>>(wq, wqS, Dn, Dn);
        wsplit_kernel<<<(nDD + 255) / 256, blk>>>(wk, wkS, Dn, Dn);
        wsplit_kernel<<<(nDD + 255) / 256, blk>>>(wv, wvS, Dn, Dn);
        wsplit_kernel<<<(nDD + 255) / 256, blk>>>(wo, woS, Dn, Dn);
        int nDH = Dn * HIDn;
        wsplit_kernel<<<(nDH + 255) / 256, blk>>>(w1, w1S, Dn, HIDn);
        wsplit_kernel<<<(nDH + 255) / 256, blk>>>(w2, w2S, HIDn, Dn);
    }

    // 1. pre-attention masked LN -> split operands
    mln_kernel<<<gLN, blk>>>(x_a, nullptr, valid_a, ln_a_g, ln_a_b, nullptr, alnS);
    mln_kernel<<<gLN, blk>>>(x_b, nullptr, valid_b, ln_b_g, ln_b_b, nullptr, blnS);

    // 2. six projections (warp MMA), one batched launch
    {
        TcBatch tb;
        tb.A[0] = alnS; tb.A[1] = alnS; tb.A[2] = alnS;
        tb.A[3] = blnS; tb.A[4] = blnS; tb.A[5] = blnS;
        tb.B[0] = wqS;  tb.B[1] = wkS;  tb.B[2] = wvS;
        tb.B[3] = wqS;  tb.B[4] = wkS;  tb.B[5] = wvS;
        tb.bias[0] = bq; tb.bias[1] = bk; tb.bias[2] = bv;
        tb.bias[3] = bq; tb.bias[4] = bk; tb.bias[5] = bv;
        tb.C[0] = Qa; tb.C[1] = Ka; tb.C[2] = Va;
        tb.C[3] = Qb; tb.C[4] = Kb; tb.C[5] = Vb;
        dim3 grid(ROWS / 128, Dn / 64, 6);
        mma_gemm_kernel<0><<<grid, blk>>>(tb, K3D, Dn);
    }

    // 3. flash attention -> split ctx
    {
        FlashArgs fa;
        fa.Q[0] = Qa; fa.K[0] = Kb; fa.V[0] = Vb; fa.vq[0] = valid_a; fa.vk[0] = valid_b; fa.ctx[0] = ctxaS;
        fa.Q[1] = Qb; fa.K[1] = Ka; fa.V[1] = Va; fa.vq[1] = valid_b; fa.vk[1] = valid_a; fa.ctx[1] = ctxbS;
        dim3 grid(Ln / 64, Bn * Hn, 2);
        flash_kernel<<<grid, blk>>>(fa);
    }

    // 4. output projection (warp MMA) + fused residual-LN + pre-FFN LN
    {
        TcBatch tb = {};
        tb.A[0] = ctxaS; tb.A[1] = ctxbS;
        tb.B[0] = woS;   tb.B[1] = woS;
        tb.bias[0] = bo; tb.bias[1] = bo;
        tb.C[0] = tmpa;  tb.C[1] = tmpb;
        dim3 grid(ROWS / 128, Dn / 64, 2);
        mma_gemm_kernel<0><<<grid, blk>>>(tb, K3D, Dn);
    }
    mln2_kernel<<<gLN, blk>>>(tmpa, x_a, valid_a, ln_oa_g, ln_oa_b, fln_g, fln_b, oa, xnaS);
    mln2_kernel<<<gLN, blk>>>(tmpb, x_b, valid_b, ln_ob_g, ln_ob_b, fln_g, fln_b, ob, xnbS);

    // 5. FFN w1 + GELU -> split hid (warp MMA)
    {
        TcBatch tb = {};
        tb.A[0] = xnaS; tb.A[1] = xnbS;
        tb.B[0] = w1S;  tb.B[1] = w1S;
        tb.bias[0] = b1; tb.bias[1] = b1;
        tb.C[0] = hidaS; tb.C[1] = hidbS;
        dim3 grid(ROWS / 128, HIDn / 64, 2);
        mma_gemm_kernel<1><<<grid, blk>>>(tb, K3D, HIDn);
    }
    // 6. FFN w2 (warp MMA)
    {
        TcBatch tb = {};
        tb.A[0] = hidaS; tb.A[1] = hidbS;
        tb.B[0] = w2S;   tb.B[1] = w2S;
        tb.bias[0] = b2; tb.bias[1] = b2;
        tb.C[0] = yba;   tb.C[1] = ybb;
        dim3 grid(ROWS / 128, Dn / 64, 2);
        mma_gemm_kernel<0><<<grid, blk>>>(tb, K3H, Dn);
    }
    // 7. final masked LN (+residual) -> fp32 outputs
    mln_kernel<<<gLN, blk>>>(yba, oa, valid_a, flno_g, flno_b, out_a, nullptr);
    mln_kernel<<<gLN, blk>>>(ybb, ob, valid_b, flno_g, flno_b, out_b, nullptr);
}

// round 8
// speedup vs baseline: 2.4470x; 1.4334x over previous
#include <cuda_runtime.h>
#include <cuda_fp16.h>
#include <math.h>
#include <cstdint>

// ---------------------------------------------------------------------------
// Problem constants
// ---------------------------------------------------------------------------
static constexpr int Bn   = 48;
static constexpr int Ln   = 512;
static constexpr int Dn   = 192;
static constexpr int Hn   = 6;
static constexpr int DKn  = 32;
static constexpr int HIDn = 768;
static constexpr int ROWS = Bn * Ln;                         // 24576
static constexpr long long BLD = (long long)ROWS * Dn;       // 4,718,592
static constexpr long long SZ_HID = (long long)ROWS * HIDn;
static constexpr float SCALE = 0.17677669529663689f;         // 1/sqrt(32)
static constexpr float EPSf  = 1e-5f;

// ---------------------------------------------------------------------------
// Static scratch
// fp32: Qa,Ka,Va,Qb,Kb,Vb,tmpa,tmpb,oa,ob,yba,ybb
// ---------------------------------------------------------------------------
__device__ float g_ws[12 * BLD];

// fp16 operand buffers (K-major)
static constexpr long long OFF_ALN  = 0;
static constexpr long long OFF_BLN  = OFF_ALN  + BLD;
static constexpr long long OFF_CTXA = OFF_BLN  + BLD;
static constexpr long long OFF_CTXB = OFF_CTXA + BLD;
static constexpr long long OFF_XNA  = OFF_CTXB + BLD;
static constexpr long long OFF_XNB  = OFF_XNA  + BLD;
static constexpr long long OFF_HIDA = OFF_XNB  + BLD;
static constexpr long long OFF_HIDB = OFF_HIDA + SZ_HID;
static constexpr long long OFF_WQ   = OFF_HIDB + SZ_HID;
static constexpr long long SZ_WDD   = (long long)Dn * Dn;
static constexpr long long OFF_WK   = OFF_WQ + SZ_WDD;
static constexpr long long OFF_WV   = OFF_WK + SZ_WDD;
static constexpr long long OFF_WO   = OFF_WV + SZ_WDD;
static constexpr long long OFF_W1   = OFF_WO + SZ_WDD;       // [768,192]
static constexpr long long SZ_WDH   = (long long)Dn * HIDn;
static constexpr long long OFF_W2   = OFF_W1 + SZ_WDH;       // [192,768]
static constexpr long long WSH_TOT  = OFF_W2 + SZ_WDH;
__device__ __half g_wsh[WSH_TOT];

// ---------------------------------------------------------------------------
// f32x2 packed helpers (SIMT flash path)
// ---------------------------------------------------------------------------
typedef unsigned long long ull;
__device__ __forceinline__ ull pk2(float lo, float hi) {
    ull r; asm("mov.b64 %0, {%1,%2};" : "=l"(r) : "f"(lo), "f"(hi)); return r;
}
__device__ __forceinline__ void upk2(ull v, float& lo, float& hi) {
    asm("mov.b64 {%0,%1}, %2;" : "=f"(lo), "=f"(hi) : "l"(v));
}
__device__ __forceinline__ ull ffma2(ull a, ull b, ull c) {
    ull d; asm("fma.rn.f32x2 %0, %1, %2, %3;" : "=l"(d) : "l"(a), "l"(b), "l"(c)); return d;
}
__device__ __forceinline__ ull fmul2(ull a, ull b) {
    ull d; asm("mul.rn.f32x2 %0, %1, %2;" : "=l"(d) : "l"(a), "l"(b)); return d;
}

// ---------------------------------------------------------------------------
// mma.sync helpers (family-generic PTX)
// ---------------------------------------------------------------------------
__device__ __forceinline__ uint32_t smem_to_u32(const void* p) {
    uint32_t a;
    asm("{ .reg .u64 t; cvta.to.shared.u64 t, %1; cvt.u32.u64 %0, t; }" : "=r"(a) : "l"(p));
    return a;
}
__device__ __forceinline__ void ldsm_x4(uint32_t& r0, uint32_t& r1, uint32_t& r2, uint32_t& r3,
                                        uint32_t addr) {
    asm volatile("ldmatrix.sync.aligned.m8n8.x4.shared.b16 {%0,%1,%2,%3}, [%4];"
                 : "=r"(r0), "=r"(r1), "=r"(r2), "=r"(r3) : "r"(addr));
}
__device__ __forceinline__ void mma_fp16(float& c0, float& c1, float& c2, float& c3,
                                         uint32_t a0, uint32_t a1, uint32_t a2, uint32_t a3,
                                         uint32_t b0, uint32_t b1) {
    asm volatile("mma.sync.aligned.m16n8k16.row.col.f32.f16.f16.f32 "
                 "{%0,%1,%2,%3}, {%4,%5,%6,%7}, {%8,%9}, {%0,%1,%2,%3};"
                 : "+f"(c0), "+f"(c1), "+f"(c2), "+f"(c3)
                 : "r"(a0), "r"(a1), "r"(a2), "r"(a3), "r"(b0), "r"(b1));
}

// ---------------------------------------------------------------------------
// Weight convert/transpose: W[K,N] fp32 -> out[N,K] fp16
// ---------------------------------------------------------------------------
__global__ void wconv_kernel(const float* __restrict__ W, __half* __restrict__ out,
                             int K, int N)
{
    int idx = blockIdx.x * 256 + threadIdx.x;
    if (idx >= K * N) return;
    int k = idx / N, n = idx % N;
    out[(long long)n * K + k] = __float2half_rn(W[idx]);
}

// ---------------------------------------------------------------------------
// Masked LayerNorm. One warp per row. fp32 out (outs null) or fp16 out.
// ---------------------------------------------------------------------------
__device__ __forceinline__ void mln_core(const float* xr, const float* rr, bool ok,
                                         const float* gamma, const float* beta,
                                         int lane, float* v)
{
    float s = 0.f;
#pragma unroll
    for (int e = 0; e < 6; e++) {
        int idx = lane + 32 * e;
        float t = xr[idx];
        if (rr) t += rr[idx];
        v[e] = t; s += t;
    }
    float s2 = 0.f;
#pragma unroll
    for (int e = 0; e < 6; e++) s2 += v[e] * v[e];
#pragma unroll
    for (int o = 16; o > 0; o >>= 1) {
        s  += __shfl_xor_sync(0xffffffffu, s,  o);
        s2 += __shfl_xor_sync(0xffffffffu, s2, o);
    }
    float mu = s * (1.f / Dn), var = s2 * (1.f / Dn) - mu * mu;
    float rstd = rsqrtf(var + EPSf);
#pragma unroll
    for (int e = 0; e < 6; e++) {
        int idx = lane + 32 * e;
        v[e] = ok ? fmaf((v[e] - mu) * rstd, gamma[idx], beta[idx]) : v[e];
    }
}

__global__ void mln_kernel(const float* __restrict__ x, const float* __restrict__ res,
                           const unsigned int* __restrict__ valid,
                           const float* __restrict__ gamma, const float* __restrict__ beta,
                           float* __restrict__ outf, __half* __restrict__ outh)
{
    int warp = threadIdx.x >> 5, lane = threadIdx.x & 31;
    int row  = blockIdx.x * 8 + warp;
    float v[6];
    mln_core(x + (long long)row * Dn, res ? res + (long long)row * Dn : nullptr,
             valid[row] != 0u, gamma, beta, lane, v);
    if (outh) {
        long long rb = (long long)row * Dn;
#pragma unroll
        for (int e = 0; e < 6; e++)
            outh[rb + lane + 32 * e] = __float2half_rn(v[e]);
    } else {
#pragma unroll
        for (int e = 0; e < 6; e++)
            outf[(long long)row * Dn + lane + 32 * e] = v[e];
    }
}

// fused: o = mln(x+res) (fp32); xn = mln(o) (fp16)
__global__ void mln2_kernel(const float* __restrict__ x, const float* __restrict__ res,
                            const unsigned int* __restrict__ valid,
                            const float* __restrict__ g1, const float* __restrict__ b1,
                            const float* __restrict__ g2, const float* __restrict__ b2,
                            float* __restrict__ o_out, __half* __restrict__ xn_out)
{
    int warp = threadIdx.x >> 5, lane = threadIdx.x & 31;
    int row  = blockIdx.x * 8 + warp;
    bool ok = valid[row] != 0u;
    float v[6];
    mln_core(x + (long long)row * Dn, res + (long long)row * Dn, ok, g1, b1, lane, v);
#pragma unroll
    for (int e = 0; e < 6; e++)
        o_out[(long long)row * Dn + lane + 32 * e] = v[e];
    float s = 0.f, s2 = 0.f;
#pragma unroll
    for (int e = 0; e < 6; e++) { s += v[e]; s2 += v[e] * v[e]; }
#pragma unroll
    for (int o = 16; o > 0; o >>= 1) {
        s  += __shfl_xor_sync(0xffffffffu, s,  o);
        s2 += __shfl_xor_sync(0xffffffffu, s2, o);
    }
    float mu = s * (1.f / Dn), var = s2 * (1.f / Dn) - mu * mu;
    float rstd = rsqrtf(var + EPSf);
    long long rb = (long long)row * Dn;
#pragma unroll
    for (int e = 0; e < 6; e++) {
        int idx = lane + 32 * e;
        float o_ = ok ? fmaf((v[e] - mu) * rstd, g2[idx], b2[idx]) : v[e];
        xn_out[rb + idx] = __float2half_rn(o_);
    }
}

// ---------------------------------------------------------------------------
// Warp-MMA GEMM: C[m,n] = sum_k A[m,k] B[n,k] + bias[n]
// A [M,Kd] fp16 K-major, B [Nt,Kd] fp16 K-major.
// Tile 128x64, BK=32, 256 threads = 8 warps (4m x 2n), warp tile 32x32.
// EPI 0: fp32 out. EPI 1: GELU + fp16 out (row stride Nt).
// ---------------------------------------------------------------------------
struct TcBatch {
    const __half* A[6];
    const __half* B[6];
    const float* bias[6];
    void* C[6];
};

template <int EPI>
__global__ __launch_bounds__(256) void mma_gemm_kernel(TcBatch tb, int Kd, int Nt)
{
    __shared__ __align__(16) __half As[2][128][40];
    __shared__ __align__(16) __half Bs[2][64][40];

    const int tid  = threadIdx.x;
    const int lane = tid & 31, wid = tid >> 5;
    const int wm = wid & 3, wn = wid >> 2;
    const int z  = blockIdx.z;
    const int bm = blockIdx.x * 128, bn = blockIdx.y * 64;

    const __half* __restrict__ Ag = tb.A[z];
    const __half* __restrict__ Bg = tb.B[z];

    const int u = tid & 3;        // 16B unit within 64B k-chunk
    const int r = tid >> 2;       // 0..63
    const __half* gA0 = Ag + (long long)(bm + r)      * Kd + u * 8;
    const __half* gA1 = Ag + (long long)(bm + r + 64) * Kd + u * 8;
    const __half* gB0 = Bg + (long long)(bn + r)      * Kd + u * 8;

    uint4 pa0 = *(const uint4*)gA0;
    uint4 pa1 = *(const uint4*)gA1;
    uint4 pb0 = *(const uint4*)gB0;
    *(uint4*)&As[0][r][u * 8]      = pa0;
    *(uint4*)&As[0][r + 64][u * 8] = pa1;
    *(uint4*)&Bs[0][r][u * 8]      = pb0;

    const int j = lane >> 3, i8 = lane & 7;
    const int aRow = (j & 1) * 8 + i8;
    const int aCol = (j >> 1) * 8;
    const int bRow = (j >> 1) * 8 + i8;
    const int bCol = (j & 1) * 8;

    const uint32_t AsB = smem_to_u32(&As[0][0][0]);
    const uint32_t BsB = smem_to_u32(&Bs[0][0][0]);

    float acc[2][4][4];
#pragma unroll
    for (int f = 0; f < 2; f++)
#pragma unroll
        for (int g = 0; g < 4; g++)
#pragma unroll
            for (int e = 0; e < 4; e++) acc[f][g][e] = 0.f;

    const int T = Kd >> 5;
    for (int t = 0; t < T; t++) {
        __syncthreads();
        const int buf = t & 1;
        if (t + 1 < T) {
            pa0 = *(const uint4*)(gA0 + (t + 1) * 32);
            pa1 = *(const uint4*)(gA1 + (t + 1) * 32);
            pb0 = *(const uint4*)(gB0 + (t + 1) * 32);
        }
        const uint32_t aBuf = AsB + buf * (128 * 40 * 2);
        const uint32_t bBuf = BsB + buf * (64 * 40 * 2);
#pragma unroll
        for (int ks = 0; ks < 2; ks++) {
            const int k0 = ks * 16;
            uint32_t a[2][4];
#pragma unroll
            for (int f = 0; f < 2; f++) {
                uint32_t ad = aBuf + (uint32_t)(((wm * 32 + f * 16 + aRow) * 40 + k0 + aCol) * 2);
                ldsm_x4(a[f][0], a[f][1], a[f][2], a[f][3], ad);
            }
            uint32_t b[4][2];
#pragma unroll
            for (int g2 = 0; g2 < 2; g2++) {
                uint32_t bd = bBuf + (uint32_t)(((wn * 32 + g2 * 16 + bRow) * 40 + k0 + bCol) * 2);
                uint32_t r0, r1, r2, r3;
                ldsm_x4(r0, r1, r2, r3, bd);
                b[g2 * 2][0] = r0; b[g2 * 2][1] = r1;
                b[g2 * 2 + 1][0] = r2; b[g2 * 2 + 1][1] = r3;
            }
#pragma unroll
            for (int f = 0; f < 2; f++)
#pragma unroll
                for (int g = 0; g < 4; g++)
                    mma_fp16(acc[f][g][0], acc[f][g][1], acc[f][g][2], acc[f][g][3],
                             a[f][0], a[f][1], a[f][2], a[f][3], b[g][0], b[g][1]);
        }
        if (t + 1 < T) {
            const int nb = buf ^ 1;
            *(uint4*)&As[nb][r][u * 8]      = pa0;
            *(uint4*)&As[nb][r + 64][u * 8] = pa1;
            *(uint4*)&Bs[nb][r][u * 8]      = pb0;
        }
    }

    const float* __restrict__ bias = tb.bias[z];
    const int mr = lane >> 2, nc = (lane & 3) * 2;
#pragma unroll
    for (int f = 0; f < 2; f++) {
#pragma unroll
        for (int g = 0; g < 4; g++) {
            const int m0 = bm + wm * 32 + f * 16 + mr;
            const int n0 = bn + wn * 32 + g * 8 + nc;
            const float bv0 = __ldg(bias + n0), bv1 = __ldg(bias + n0 + 1);
            float v00 = acc[f][g][0] + bv0, v01 = acc[f][g][1] + bv1;
            float v10 = acc[f][g][2] + bv0, v11 = acc[f][g][3] + bv1;
            if (EPI == 0) {
                float* C = (float*)tb.C[z];
                *(float2*)(C + (long long)m0 * Nt + n0)       = make_float2(v00, v01);
                *(float2*)(C + (long long)(m0 + 8) * Nt + n0) = make_float2(v10, v11);
            } else {
                v00 *= normcdff(v00); v01 *= normcdff(v01);
                v10 *= normcdff(v10); v11 *= normcdff(v11);
                __half* C = (__half*)tb.C[z];
                __half2 p0; p0.x = __float2half_rn(v00); p0.y = __float2half_rn(v01);
                __half2 p1; p1.x = __float2half_rn(v10); p1.y = __float2half_rn(v11);
                *(__half2*)(C + (long long)m0 * Nt + n0)       = p0;
                *(__half2*)(C + (long long)(m0 + 8) * Nt + n0) = p1;
            }
        }
    }
}

// ---------------------------------------------------------------------------
// Flash attention (SIMT fp32 math), ctx emitted as fp16 K-major.
// ---------------------------------------------------------------------------
struct FlashArgs {
    const float* Q[2];
    const float* K[2];
    const float* V[2];
    const unsigned int* vq[2];
    const unsigned int* vk[2];
    __half* ctx[2];
};

__global__ __launch_bounds__(256) void flash_kernel(FlashArgs fa)
{
    __shared__ __align__(16) float Qs[32][68];
    __shared__ __align__(16) float Ks[32][68];
    __shared__ __align__(16) float Vs[64][34];
    __shared__ __align__(16) float Ps[64][68];
    __shared__ unsigned char vqs[64];
    __shared__ unsigned char vks[64];

    const int tid = threadIdx.x;
    const int tx = tid & 15, ty = tid >> 4;
    const int qt = blockIdx.x;
    const int bh = blockIdx.y;
    const int z  = blockIdx.z;
    const int b = bh / Hn, h = bh % Hn;

    const float* Qb = fa.Q[z] + (long long)b * Ln * Dn + h * DKn;
    const float* Kb = fa.K[z] + (long long)b * Ln * Dn + h * DKn;
    const float* Vb = fa.V[z] + (long long)b * Ln * Dn + h * DKn;
    const unsigned int* vq = fa.vq[z];
    const unsigned int* vk = fa.vk[z];
    __half* ctx = fa.ctx[z];

    const int ld = tid & 31, lr = tid >> 5;

#pragma unroll
    for (int i = 0; i < 8; i++) {
        int rr = lr + i * 8;
        Qs[ld][rr] = Qb[(long long)(qt * 64 + rr) * Dn + ld] * SCALE;
        Ks[ld][rr] = Kb[(long long)rr * Dn + ld];
        Vs[rr][ld] = Vb[(long long)rr * Dn + ld];
    }
    if (tid < 64)       vqs[tid]      = (vq[b * Ln + qt * 64 + tid] != 0u) ? 1 : 0;
    else if (tid < 128) vks[tid - 64] = (vk[b * Ln + tid - 64]      != 0u) ? 1 : 0;
    __syncthreads();

    ull   o2[4]   = {0ull, 0ull, 0ull, 0ull};
    float mrow[4] = {-INFINITY, -INFINITY, -INFINITY, -INFINITY};
    float lrow[4] = {0.f, 0.f, 0.f, 0.f};

    float kreg[8], vreg[8];
    unsigned int vkr = 0u;

    for (int t = 0; t < 8; t++) {
        ull s01[4] = {0ull, 0ull, 0ull, 0ull};
        ull s23[4] = {0ull, 0ull, 0ull, 0ull};
#pragma unroll
        for (int k = 0; k < 32; k++) {
            float4 aq = *(const float4*)&Qs[k][ty * 4];
            const ull* bp = (const ull*)&Ks[k][tx * 4];
            ull b01 = bp[0], b23 = bp[1];
            ull a;
            a = pk2(aq.x, aq.x); s01[0] = ffma2(a, b01, s01[0]); s23[0] = ffma2(a, b23, s23[0]);
            a = pk2(aq.y, aq.y); s01[1] = ffma2(a, b01, s01[1]); s23[1] = ffma2(a, b23, s23[1]);
            a = pk2(aq.z, aq.z); s01[2] = ffma2(a, b01, s01[2]); s23[2] = ffma2(a, b23, s23[2]);
            a = pk2(aq.w, aq.w); s01[3] = ffma2(a, b01, s01[3]); s23[3] = ffma2(a, b23, s23[3]);
        }

        if (t < 7) {
#pragma unroll
            for (int i = 0; i < 8; i++) {
                int rr = (t + 1) * 64 + lr + i * 8;
                kreg[i] = Kb[(long long)rr * Dn + ld];
                vreg[i] = Vb[(long long)rr * Dn + ld];
            }
            if (tid < 64) vkr = vk[b * Ln + (t + 1) * 64 + tid];
        }

        float s[4][4];
#pragma unroll
        for (int i = 0; i < 4; i++) {
            upk2(s01[i], s[i][0], s[i][1]);
            upk2(s23[i], s[i][2], s[i][3]);
            bool qok = vqs[ty * 4 + i] != 0;
#pragma unroll
            for (int jj = 0; jj < 4; jj++)
                if (!(qok && vks[tx * 4 + jj])) s[i][jj] = -1e9f;
        }
#pragma unroll
        for (int i = 0; i < 4; i++) {
            float tm = fmaxf(fmaxf(s[i][0], s[i][1]), fmaxf(s[i][2], s[i][3]));
#pragma unroll
            for (int o = 8; o > 0; o >>= 1)
                tm = fmaxf(tm, __shfl_xor_sync(0xffffffffu, tm, o));
            float nm = fmaxf(mrow[i], tm);
            float p0 = __expf(s[i][0] - nm);
            float p1 = __expf(s[i][1] - nm);
            float p2 = __expf(s[i][2] - nm);
            float p3 = __expf(s[i][3] - nm);
            float ts = (p0 + p1) + (p2 + p3);
#pragma unroll
            for (int o = 8; o > 0; o >>= 1)
                ts += __shfl_xor_sync(0xffffffffu, ts, o);
            float fac = __expf(mrow[i] - nm);
            lrow[i] = lrow[i] * fac + ts;
            mrow[i] = nm;
            o2[i] = fmul2(o2[i], pk2(fac, fac));
            *(float4*)&Ps[ty * 4 + i][tx * 4] = make_float4(p0, p1, p2, p3);
        }
        __syncthreads();

#pragma unroll 4
        for (int jj = 0; jj < 64; jj++) {
            ull v2 = *(const ull*)&Vs[jj][tx * 2];
#pragma unroll
            for (int i = 0; i < 4; i++) {
                float p = Ps[ty * 4 + i][jj];
                o2[i] = ffma2(pk2(p, p), v2, o2[i]);
            }
        }
        __syncthreads();

        if (t < 7) {
#pragma unroll
            for (int i = 0; i < 8; i++) {
                int rr = lr + i * 8;
                Ks[ld][rr] = kreg[i];
                Vs[rr][ld] = vreg[i];
            }
            if (tid < 64) vks[tid] = (vkr != 0u) ? 1 : 0;
            __syncthreads();
        }
    }

#pragma unroll
    for (int i = 0; i < 4; i++) {
        float o0, o1;
        upk2(o2[i], o0, o1);
        float inv = 1.f / lrow[i];
        o0 *= inv; o1 *= inv;
        long long row = (long long)b * Ln + qt * 64 + ty * 4 + i;
        __half2 p; p.x = __float2half_rn(o0); p.y = __float2half_rn(o1);
        *(__half2*)(ctx + row * Dn + h * DKn + tx * 2) = p;
    }
}

// ---------------------------------------------------------------------------
// Host launcher
// ---------------------------------------------------------------------------
extern "C" void kernel_launch(void* const* d_in, const int* in_sizes, int n_in,
                              void* d_out, int out_size)
{
    const float* x_a = (const float*)d_in[0];
    const float* x_b = (const float*)d_in[1];
    const unsigned int* valid_a = (const unsigned int*)d_in[2];
    const unsigned int* valid_b = (const unsigned int*)d_in[3];
    const float* ln_a_g  = (const float*)d_in[4];
    const float* ln_a_b  = (const float*)d_in[5];
    const float* ln_b_g  = (const float*)d_in[6];
    const float* ln_b_b  = (const float*)d_in[7];
    const float* ln_oa_g = (const float*)d_in[8];
    const float* ln_oa_b = (const float*)d_in[9];
    const float* ln_ob_g = (const float*)d_in[10];
    const float* ln_ob_b = (const float*)d_in[11];
    const float* wq = (const float*)d_in[12];
    const float* bq = (const float*)d_in[13];
    const float* wk = (const float*)d_in[14];
    const float* bk = (const float*)d_in[15];
    const float* wv = (const float*)d_in[16];
    const float* bv = (const float*)d_in[17];
    const float* wo = (const float*)d_in[18];
    const float* bo = (const float*)d_in[19];
    const float* fln_g  = (const float*)d_in[20];
    const float* fln_b  = (const float*)d_in[21];
    const float* flno_g = (const float*)d_in[22];
    const float* flno_b = (const float*)d_in[23];
    const float* w1 = (const float*)d_in[24];
    const float* b1 = (const float*)d_in[25];
    const float* w2 = (const float*)d_in[26];
    const float* b2 = (const float*)d_in[27];

    float* ws = nullptr;
    cudaGetSymbolAddress((void**)&ws, g_ws);
    __half* wh = nullptr;
    cudaGetSymbolAddress((void**)&wh, g_wsh);

    float* Qa   = ws + 0 * BLD;
    float* Ka   = ws + 1 * BLD;
    float* Va   = ws + 2 * BLD;
    float* Qb   = ws + 3 * BLD;
    float* Kb   = ws + 4 * BLD;
    float* Vb   = ws + 5 * BLD;
    float* tmpa = ws + 6 * BLD;
    float* tmpb = ws + 7 * BLD;
    float* oa   = ws + 8 * BLD;
    float* ob   = ws + 9 * BLD;
    float* yba  = ws + 10 * BLD;
    float* ybb  = ws + 11 * BLD;

    __half* alnH  = wh + OFF_ALN;
    __half* blnH  = wh + OFF_BLN;
    __half* ctxaH = wh + OFF_CTXA;
    __half* ctxbH = wh + OFF_CTXB;
    __half* xnaH  = wh + OFF_XNA;
    __half* xnbH  = wh + OFF_XNB;
    __half* hidaH = wh + OFF_HIDA;
    __half* hidbH = wh + OFF_HIDB;
    __half* wqH   = wh + OFF_WQ;
    __half* wkH   = wh + OFF_WK;
    __half* wvH   = wh + OFF_WV;
    __half* woH   = wh + OFF_WO;
    __half* w1H   = wh + OFF_W1;
    __half* w2H   = wh + OFF_W2;

    float* out_a = (float*)d_out;
    float* out_b = (float*)d_out + BLD;

    dim3 blk(256);
    dim3 gLN(ROWS / 8);

    // 0. weight conversions (transpose to [N,K] fp16)
    {
        int nDD = Dn * Dn;
        wconv_kernel<<<(nDD + 255) / 256, blk>>>(wq, wqH, Dn, Dn);
        wconv_kernel<<<(nDD + 255) / 256, blk>>>(wk, wkH, Dn, Dn);
        wconv_kernel<<<(nDD + 255) / 256, blk>>>(wv, wvH, Dn, Dn);
        wconv_kernel<<<(nDD + 255) / 256, blk>>>(wo, woH, Dn, Dn);
        int nDH = Dn * HIDn;
        wconv_kernel<<<(nDH + 255) / 256, blk>>>(w1, w1H, Dn, HIDn);
        wconv_kernel<<<(nDH + 255) / 256, blk>>>(w2, w2H, HIDn, Dn);
    }

    // 1. pre-attention masked LN -> fp16 operands
    mln_kernel<<<gLN, blk>>>(x_a, nullptr, valid_a, ln_a_g, ln_a_b, nullptr, alnH);
    mln_kernel<<<gLN, blk>>>(x_b, nullptr, valid_b, ln_b_g, ln_b_b, nullptr, blnH);

    // 2. six projections (warp MMA), one batched launch
    {
        TcBatch tb;
        tb.A[0] = alnH; tb.A[1] = alnH; tb.A[2] = alnH;
        tb.A[3] = blnH; tb.A[4] = blnH; tb.A[5] = blnH;
        tb.B[0] = wqH;  tb.B[1] = wkH;  tb.B[2] = wvH;
        tb.B[3] = wqH;  tb.B[4] = wkH;  tb.B[5] = wvH;
        tb.bias[0] = bq; tb.bias[1] = bk; tb.bias[2] = bv;
        tb.bias[3] = bq; tb.bias[4] = bk; tb.bias[5] = bv;
        tb.C[0] = Qa; tb.C[1] = Ka; tb.C[2] = Va;
        tb.C[3] = Qb; tb.C[4] = Kb; tb.C[5] = Vb;
        dim3 grid(ROWS / 128, Dn / 64, 6);
        mma_gemm_kernel<0><<<grid, blk>>>(tb, Dn, Dn);
    }

    // 3. flash attention -> fp16 ctx
    {
        FlashArgs fa;
        fa.Q[0] = Qa; fa.K[0] = Kb; fa.V[0] = Vb; fa.vq[0] = valid_a; fa.vk[0] = valid_b; fa.ctx[0] = ctxaH;
        fa.Q[1] = Qb; fa.K[1] = Ka; fa.V[1] = Va; fa.vq[1] = valid_b; fa.vk[1] = valid_a; fa.ctx[1] = ctxbH;
        dim3 grid(Ln / 64, Bn * Hn, 2);
        flash_kernel<<<grid, blk>>>(fa);
    }

    // 4. output projection (warp MMA) + fused residual-LN + pre-FFN LN
    {
        TcBatch tb = {};
        tb.A[0] = ctxaH; tb.A[1] = ctxbH;
        tb.B[0] = woH;   tb.B[1] = woH;
        tb.bias[0] = bo; tb.bias[1] = bo;
        tb.C[0] = tmpa;  tb.C[1] = tmpb;
        dim3 grid(ROWS / 128, Dn / 64, 2);
        mma_gemm_kernel<0><<<grid, blk>>>(tb, Dn, Dn);
    }
    mln2_kernel<<<gLN, blk>>>(tmpa, x_a, valid_a, ln_oa_g, ln_oa_b, fln_g, fln_b, oa, xnaH);
    mln2_kernel<<<gLN, blk>>>(tmpb, x_b, valid_b, ln_ob_g, ln_ob_b, fln_g, fln_b, ob, xnbH);

    // 5. FFN w1 + GELU -> fp16 hid (warp MMA)
    {
        TcBatch tb = {};
        tb.A[0] = xnaH; tb.A[1] = xnbH;
        tb.B[0] = w1H;  tb.B[1] = w1H;
        tb.bias[0] = b1; tb.bias[1] = b1;
        tb.C[0] = hidaH; tb.C[1] = hidbH;
        dim3 grid(ROWS / 128, HIDn / 64, 2);
        mma_gemm_kernel<1><<<grid, blk>>>(tb, Dn, HIDn);
    }
    // 6. FFN w2 (warp MMA)
    {
        TcBatch tb = {};
        tb.A[0] = hidaH; tb.A[1] = hidbH;
        tb.B[0] = w2H;   tb.B[1] = w2H;
        tb.bias[0] = b2; tb.bias[1] = b2;
        tb.C[0] = yba;   tb.C[1] = ybb;
        dim3 grid(ROWS / 128, Dn / 64, 2);
        mma_gemm_kernel<0><<<grid, blk>>>(tb, HIDn, Dn);
    }
    // 7. final masked LN (+residual) -> fp32 outputs
    mln_kernel<<<gLN, blk>>>(yba, oa, valid_a, flno_g, flno_b, out_a, nullptr);
    mln_kernel<<<gLN, blk>>>(ybb, ob, valid_b, flno_g, flno_b, out_b, nullptr);
}

// round 9
// speedup vs baseline: 5.0469x; 2.0625x over previous
#include <cuda_runtime.h>
#include <cuda_fp16.h>
#include <math.h>
#include <cstdint>

// ---------------------------------------------------------------------------
// Problem constants
// ---------------------------------------------------------------------------
static constexpr int Bn   = 48;
static constexpr int Ln   = 512;
static constexpr int Dn   = 192;
static constexpr int Hn   = 6;
static constexpr int DKn  = 32;
static constexpr int HIDn = 768;
static constexpr int ROWS = Bn * Ln;                         // 24576
static constexpr long long BLD = (long long)ROWS * Dn;       // 4,718,592
static constexpr long long SZ_HID = (long long)ROWS * HIDn;
static constexpr float SCALE = 0.17677669529663689f;         // 1/sqrt(32)
static constexpr float EPSf  = 1e-5f;

// ---------------------------------------------------------------------------
// Static scratch
// fp32: tmpa,tmpb,oa,ob,yba,ybb
// ---------------------------------------------------------------------------
__device__ float g_ws[6 * BLD];

// fp16 buffers (all K-major)
static constexpr long long OFF_ALN  = 0;
static constexpr long long OFF_BLN  = OFF_ALN  + BLD;
static constexpr long long OFF_CTXA = OFF_BLN  + BLD;
static constexpr long long OFF_CTXB = OFF_CTXA + BLD;
static constexpr long long OFF_XNA  = OFF_CTXB + BLD;
static constexpr long long OFF_XNB  = OFF_XNA  + BLD;
static constexpr long long OFF_QA   = OFF_XNB  + BLD;
static constexpr long long OFF_KA   = OFF_QA   + BLD;
static constexpr long long OFF_VA   = OFF_KA   + BLD;
static constexpr long long OFF_QB   = OFF_VA   + BLD;
static constexpr long long OFF_KB   = OFF_QB   + BLD;
static constexpr long long OFF_VB   = OFF_KB   + BLD;
static constexpr long long OFF_HIDA = OFF_VB   + BLD;
static constexpr long long OFF_HIDB = OFF_HIDA + SZ_HID;
static constexpr long long OFF_WQ   = OFF_HIDB + SZ_HID;
static constexpr long long SZ_WDD   = (long long)Dn * Dn;
static constexpr long long OFF_WK   = OFF_WQ + SZ_WDD;
static constexpr long long OFF_WV   = OFF_WK + SZ_WDD;
static constexpr long long OFF_WO   = OFF_WV + SZ_WDD;
static constexpr long long OFF_W1   = OFF_WO + SZ_WDD;
static constexpr long long SZ_WDH   = (long long)Dn * HIDn;
static constexpr long long OFF_W2   = OFF_W1 + SZ_WDH;
static constexpr long long WSH_TOT  = OFF_W2 + SZ_WDH;
__device__ __half g_wsh[WSH_TOT];

// ---------------------------------------------------------------------------
// mma.sync helpers (family-generic PTX)
// ---------------------------------------------------------------------------
__device__ __forceinline__ uint32_t smem_to_u32(const void* p) {
    uint32_t a;
    asm("{ .reg .u64 t; cvta.to.shared.u64 t, %1; cvt.u32.u64 %0, t; }" : "=r"(a) : "l"(p));
    return a;
}
__device__ __forceinline__ void ldsm_x4(uint32_t& r0, uint32_t& r1, uint32_t& r2, uint32_t& r3,
                                        uint32_t addr) {
    asm volatile("ldmatrix.sync.aligned.m8n8.x4.shared.b16 {%0,%1,%2,%3}, [%4];"
                 : "=r"(r0), "=r"(r1), "=r"(r2), "=r"(r3) : "r"(addr));
}
__device__ __forceinline__ void mma_fp16(float& c0, float& c1, float& c2, float& c3,
                                         uint32_t a0, uint32_t a1, uint32_t a2, uint32_t a3,
                                         uint32_t b0, uint32_t b1) {
    asm volatile("mma.sync.aligned.m16n8k16.row.col.f32.f16.f16.f32 "
                 "{%0,%1,%2,%3}, {%4,%5,%6,%7}, {%8,%9}, {%0,%1,%2,%3};"
                 : "+f"(c0), "+f"(c1), "+f"(c2), "+f"(c3)
                 : "r"(a0), "r"(a1), "r"(a2), "r"(a3), "r"(b0), "r"(b1));
}
__device__ __forceinline__ uint32_t h2pack(float a, float b) {
    __half2 h = __floats2half2_rn(a, b);
    return *(uint32_t*)&h;
}

// ---------------------------------------------------------------------------
// Weight convert/transpose: W[K,N] fp32 -> out[N,K] fp16
// ---------------------------------------------------------------------------
__global__ void wconv_kernel(const float* __restrict__ W, __half* __restrict__ out,
                             int K, int N)
{
    int idx = blockIdx.x * 256 + threadIdx.x;
    if (idx >= K * N) return;
    int k = idx / N, n = idx % N;
    out[(long long)n * K + k] = __float2half_rn(W[idx]);
}

// ---------------------------------------------------------------------------
// Masked LayerNorm. One warp per row. fp32 out (outh null) or fp16 out.
// ---------------------------------------------------------------------------
__device__ __forceinline__ void mln_core(const float* xr, const float* rr, bool ok,
                                         const float* gamma, const float* beta,
                                         int lane, float* v)
{
    float s = 0.f;
#pragma unroll
    for (int e = 0; e < 6; e++) {
        int idx = lane + 32 * e;
        float t = xr[idx];
        if (rr) t += rr[idx];
        v[e] = t; s += t;
    }
    float s2 = 0.f;
#pragma unroll
    for (int e = 0; e < 6; e++) s2 += v[e] * v[e];
#pragma unroll
    for (int o = 16; o > 0; o >>= 1) {
        s  += __shfl_xor_sync(0xffffffffu, s,  o);
        s2 += __shfl_xor_sync(0xffffffffu, s2, o);
    }
    float mu = s * (1.f / Dn), var = s2 * (1.f / Dn) - mu * mu;
    float rstd = rsqrtf(var + EPSf);
#pragma unroll
    for (int e = 0; e < 6; e++) {
        int idx = lane + 32 * e;
        v[e] = ok ? fmaf((v[e] - mu) * rstd, gamma[idx], beta[idx]) : v[e];
    }
}

__global__ void mln_kernel(const float* __restrict__ x, const float* __restrict__ res,
                           const unsigned int* __restrict__ valid,
                           const float* __restrict__ gamma, const float* __restrict__ beta,
                           float* __restrict__ outf, __half* __restrict__ outh)
{
    int warp = threadIdx.x >> 5, lane = threadIdx.x & 31;
    int row  = blockIdx.x * 8 + warp;
    float v[6];
    mln_core(x + (long long)row * Dn, res ? res + (long long)row * Dn : nullptr,
             valid[row] != 0u, gamma, beta, lane, v);
    if (outh) {
        long long rb = (long long)row * Dn;
#pragma unroll
        for (int e = 0; e < 6; e++)
            outh[rb + lane + 32 * e] = __float2half_rn(v[e]);
    } else {
#pragma unroll
        for (int e = 0; e < 6; e++)
            outf[(long long)row * Dn + lane + 32 * e] = v[e];
    }
}

// fused: o = mln(x+res) (fp32); xn = mln(o) (fp16)
__global__ void mln2_kernel(const float* __restrict__ x, const float* __restrict__ res,
                            const unsigned int* __restrict__ valid,
                            const float* __restrict__ g1, const float* __restrict__ b1,
                            const float* __restrict__ g2, const float* __restrict__ b2,
                            float* __restrict__ o_out, __half* __restrict__ xn_out)
{
    int warp = threadIdx.x >> 5, lane = threadIdx.x & 31;
    int row  = blockIdx.x * 8 + warp;
    bool ok = valid[row] != 0u;
    float v[6];
    mln_core(x + (long long)row * Dn, res + (long long)row * Dn, ok, g1, b1, lane, v);
#pragma unroll
    for (int e = 0; e < 6; e++)
        o_out[(long long)row * Dn + lane + 32 * e] = v[e];
    float s = 0.f, s2 = 0.f;
#pragma unroll
    for (int e = 0; e < 6; e++) { s += v[e]; s2 += v[e] * v[e]; }
#pragma unroll
    for (int o = 16; o > 0; o >>= 1) {
        s  += __shfl_xor_sync(0xffffffffu, s,  o);
        s2 += __shfl_xor_sync(0xffffffffu, s2, o);
    }
    float mu = s * (1.f / Dn), var = s2 * (1.f / Dn) - mu * mu;
    float rstd = rsqrtf(var + EPSf);
    long long rb = (long long)row * Dn;
#pragma unroll
    for (int e = 0; e < 6; e++) {
        int idx = lane + 32 * e;
        float o_ = ok ? fmaf((v[e] - mu) * rstd, g2[idx], b2[idx]) : v[e];
        xn_out[rb + idx] = __float2half_rn(o_);
    }
}

// ---------------------------------------------------------------------------
// Warp-MMA GEMM: C[m,n] = sum_k A[m,k] B[n,k] + bias[n]
// EPI 0: fp32 out. EPI 1: GELU + fp16 out. EPI 2: fp16 out.
// ---------------------------------------------------------------------------
struct TcBatch {
    const __half* A[6];
    const __half* B[6];
    const float* bias[6];
    void* C[6];
};

template <int EPI>
__global__ __launch_bounds__(256) void mma_gemm_kernel(TcBatch tb, int Kd, int Nt)
{
    __shared__ __align__(16) __half As[2][128][40];
    __shared__ __align__(16) __half Bs[2][64][40];

    const int tid  = threadIdx.x;
    const int lane = tid & 31, wid = tid >> 5;
    const int wm = wid & 3, wn = wid >> 2;
    const int z  = blockIdx.z;
    const int bm = blockIdx.x * 128, bn = blockIdx.y * 64;

    const __half* __restrict__ Ag = tb.A[z];
    const __half* __restrict__ Bg = tb.B[z];

    const int u = tid & 3;
    const int r = tid >> 2;
    const __half* gA0 = Ag + (long long)(bm + r)      * Kd + u * 8;
    const __half* gA1 = Ag + (long long)(bm + r + 64) * Kd + u * 8;
    const __half* gB0 = Bg + (long long)(bn + r)      * Kd + u * 8;

    uint4 pa0 = *(const uint4*)gA0;
    uint4 pa1 = *(const uint4*)gA1;
    uint4 pb0 = *(const uint4*)gB0;
    *(uint4*)&As[0][r][u * 8]      = pa0;
    *(uint4*)&As[0][r + 64][u * 8] = pa1;
    *(uint4*)&Bs[0][r][u * 8]      = pb0;

    const int j = lane >> 3, i8 = lane & 7;
    const int aRow = (j & 1) * 8 + i8;
    const int aCol = (j >> 1) * 8;
    const int bRow = (j >> 1) * 8 + i8;
    const int bCol = (j & 1) * 8;

    const uint32_t AsB = smem_to_u32(&As[0][0][0]);
    const uint32_t BsB = smem_to_u32(&Bs[0][0][0]);

    float acc[2][4][4];
#pragma unroll
    for (int f = 0; f < 2; f++)
#pragma unroll
        for (int g = 0; g < 4; g++)
#pragma unroll
            for (int e = 0; e < 4; e++) acc[f][g][e] = 0.f;

    const int T = Kd >> 5;
    for (int t = 0; t < T; t++) {
        __syncthreads();
        const int buf = t & 1;
        if (t + 1 < T) {
            pa0 = *(const uint4*)(gA0 + (t + 1) * 32);
            pa1 = *(const uint4*)(gA1 + (t + 1) * 32);
            pb0 = *(const uint4*)(gB0 + (t + 1) * 32);
        }
        const uint32_t aBuf = AsB + buf * (128 * 40 * 2);
        const uint32_t bBuf = BsB + buf * (64 * 40 * 2);
#pragma unroll
        for (int ks = 0; ks < 2; ks++) {
            const int k0 = ks * 16;
            uint32_t a[2][4];
#pragma unroll
            for (int f = 0; f < 2; f++) {
                uint32_t ad = aBuf + (uint32_t)(((wm * 32 + f * 16 + aRow) * 40 + k0 + aCol) * 2);
                ldsm_x4(a[f][0], a[f][1], a[f][2], a[f][3], ad);
            }
            uint32_t b[4][2];
#pragma unroll
            for (int g2 = 0; g2 < 2; g2++) {
                uint32_t bd = bBuf + (uint32_t)(((wn * 32 + g2 * 16 + bRow) * 40 + k0 + bCol) * 2);
                uint32_t r0, r1, r2, r3;
                ldsm_x4(r0, r1, r2, r3, bd);
                b[g2 * 2][0] = r0; b[g2 * 2][1] = r1;
                b[g2 * 2 + 1][0] = r2; b[g2 * 2 + 1][1] = r3;
            }
#pragma unroll
            for (int f = 0; f < 2; f++)
#pragma unroll
                for (int g = 0; g < 4; g++)
                    mma_fp16(acc[f][g][0], acc[f][g][1], acc[f][g][2], acc[f][g][3],
                             a[f][0], a[f][1], a[f][2], a[f][3], b[g][0], b[g][1]);
        }
        if (t + 1 < T) {
            const int nb = buf ^ 1;
            *(uint4*)&As[nb][r][u * 8]      = pa0;
            *(uint4*)&As[nb][r + 64][u * 8] = pa1;
            *(uint4*)&Bs[nb][r][u * 8]      = pb0;
        }
    }

    const float* __restrict__ bias = tb.bias[z];
    const int mr = lane >> 2, nc = (lane & 3) * 2;
#pragma unroll
    for (int f = 0; f < 2; f++) {
#pragma unroll
        for (int g = 0; g < 4; g++) {
            const int m0 = bm + wm * 32 + f * 16 + mr;
            const int n0 = bn + wn * 32 + g * 8 + nc;
            const float bv0 = __ldg(bias + n0), bv1 = __ldg(bias + n0 + 1);
            float v00 = acc[f][g][0] + bv0, v01 = acc[f][g][1] + bv1;
            float v10 = acc[f][g][2] + bv0, v11 = acc[f][g][3] + bv1;
            if (EPI == 0) {
                float* C = (float*)tb.C[z];
                *(float2*)(C + (long long)m0 * Nt + n0)       = make_float2(v00, v01);
                *(float2*)(C + (long long)(m0 + 8) * Nt + n0) = make_float2(v10, v11);
            } else {
                if (EPI == 1) {
                    v00 *= normcdff(v00); v01 *= normcdff(v01);
                    v10 *= normcdff(v10); v11 *= normcdff(v11);
                }
                __half* C = (__half*)tb.C[z];
                __half2 p0 = __floats2half2_rn(v00, v01);
                __half2 p1 = __floats2half2_rn(v10, v11);
                *(__half2*)(C + (long long)m0 * Nt + n0)       = p0;
                *(__half2*)(C + (long long)(m0 + 8) * Nt + n0) = p1;
            }
        }
    }
}

// ---------------------------------------------------------------------------
// Flash attention with tensor-core MMA (fp16 in, fp32 acc).
// Block: 128 threads = 4 warps, q-tile 64 rows, each warp 16 rows.
// Per 64-key tile: S = Q K^T (mma), warp-local online softmax, O += P V (mma,
// P stays in registers as A-fragments).
// ---------------------------------------------------------------------------
struct FlashArgs {
    const __half* Q[2];
    const __half* K[2];
    const __half* V[2];
    const unsigned int* vq[2];
    const unsigned int* vk[2];
    __half* ctx[2];
};

__global__ __launch_bounds__(128) void flash_mma_kernel(FlashArgs fa)
{
    __shared__ __align__(16) __half Qs[64][40];
    __shared__ __align__(16) __half Ks[2][64][40];
    __shared__ __align__(16) __half VTs[2][32][72];
    __shared__ unsigned char vqs[64];
    __shared__ unsigned char vks[2][64];

    const int tid = threadIdx.x;
    const int lane = tid & 31, wid = tid >> 5;
    const int qt = blockIdx.x, bh = blockIdx.y, z = blockIdx.z;
    const int b = bh / Hn, h = bh % Hn;

    const __half* Qg = fa.Q[z] + (long long)b * Ln * Dn + h * DKn;
    const __half* Kg = fa.K[z] + (long long)b * Ln * Dn + h * DKn;
    const __half* Vg = fa.V[z] + (long long)b * Ln * Dn + h * DKn;
    const unsigned int* vq = fa.vq[z] + b * Ln;
    const unsigned int* vk = fa.vk[z] + b * Ln;
    __half* ctx = fa.ctx[z];

    const int r4 = tid >> 2, u4 = tid & 3;

    // Q tile + K/VT tile 0 + masks
#pragma unroll
    for (int jj = 0; jj < 2; jj++) {
        int row = r4 + jj * 32;
        *(uint4*)&Qs[row][u4 * 8]    = *(const uint4*)(Qg + (long long)(qt * 64 + row) * Dn + u4 * 8);
        *(uint4*)&Ks[0][row][u4 * 8] = *(const uint4*)(Kg + (long long)row * Dn + u4 * 8);
    }
#pragma unroll
    for (int jj = 0; jj < 8; jj++) {
        int idx = tid + jj * 128;
        int d2 = idx & 15, jrow = idx >> 4;
        __half2 v = *(const __half2*)(Vg + (long long)jrow * Dn + d2 * 2);
        VTs[0][d2 * 2][jrow]     = v.x;
        VTs[0][d2 * 2 + 1][jrow] = v.y;
    }
    if (tid < 64) {
        vqs[tid]    = (vq[qt * 64 + tid] != 0u) ? 1 : 0;
        vks[0][tid] = (vk[tid] != 0u) ? 1 : 0;
    }
    __syncthreads();

    const int j = lane >> 3, i8 = lane & 7;
    const int aRow = (j & 1) * 8 + i8;
    const int aCol = (j >> 1) * 8;
    const int bRow = (j >> 1) * 8 + i8;
    const int bCol = (j & 1) * 8;

    const uint32_t QsB = smem_to_u32(&Qs[0][0]);
    const uint32_t KsB = smem_to_u32(&Ks[0][0][0]);
    const uint32_t VTB = smem_to_u32(&VTs[0][0][0]);

    float mrow0 = -INFINITY, mrow1 = -INFINITY;
    float lrow0 = 0.f, lrow1 = 0.f;
    float oacc[4][4];
#pragma unroll
    for (int g = 0; g < 4; g++)
#pragma unroll
        for (int e = 0; e < 4; e++) oacc[g][e] = 0.f;

    const int lr = lane >> 2;
    const bool qok0 = vqs[wid * 16 + lr] != 0;
    const bool qok1 = vqs[wid * 16 + lr + 8] != 0;

    uint4 kpre[2];
    __half2 vpre[8];
    unsigned char vkpre = 0;

    for (int t = 0; t < 8; t++) {
        const int buf = t & 1;

        // ---- S = Q K^T (16x64 per warp) ----
        float sf[8][4];
#pragma unroll
        for (int g = 0; g < 8; g++)
#pragma unroll
            for (int e = 0; e < 4; e++) sf[g][e] = 0.f;

#pragma unroll
        for (int ks = 0; ks < 2; ks++) {
            const int k0 = ks * 16;
            uint32_t a0, a1, a2, a3;
            ldsm_x4(a0, a1, a2, a3,
                    QsB + (uint32_t)(((wid * 16 + aRow) * 40 + k0 + aCol) * 2));
#pragma unroll
            for (int g2 = 0; g2 < 4; g2++) {
                uint32_t r0, r1, r2, r3;
                ldsm_x4(r0, r1, r2, r3,
                        KsB + (uint32_t)((buf * 64 * 40 + (g2 * 16 + bRow) * 40 + k0 + bCol) * 2));
                mma_fp16(sf[g2 * 2][0], sf[g2 * 2][1], sf[g2 * 2][2], sf[g2 * 2][3],
                         a0, a1, a2, a3, r0, r1);
                mma_fp16(sf[g2 * 2 + 1][0], sf[g2 * 2 + 1][1], sf[g2 * 2 + 1][2], sf[g2 * 2 + 1][3],
                         a0, a1, a2, a3, r2, r3);
            }
        }

        // ---- prefetch next K/VT tile into registers ----
        if (t < 7) {
#pragma unroll
            for (int jj = 0; jj < 2; jj++) {
                int row = (t + 1) * 64 + r4 + jj * 32;
                kpre[jj] = *(const uint4*)(Kg + (long long)row * Dn + u4 * 8);
            }
#pragma unroll
            for (int jj = 0; jj < 8; jj++) {
                int idx = tid + jj * 128;
                int d2 = idx & 15, jrow = idx >> 4;
                vpre[jj] = *(const __half2*)(Vg + (long long)((t + 1) * 64 + jrow) * Dn + d2 * 2);
            }
            if (tid < 64) vkpre = (vk[(t + 1) * 64 + tid] != 0u) ? 1 : 0;
        }

        // ---- mask + online softmax (warp-local; rows in lane quads) ----
        float rmax0 = -INFINITY, rmax1 = -INFINITY;
#pragma unroll
        for (int g = 0; g < 8; g++) {
            int c0 = g * 8 + (lane & 3) * 2;
            bool k0ok = vks[buf][c0] != 0, k1ok = vks[buf][c0 + 1] != 0;
            sf[g][0] = (qok0 && k0ok) ? sf[g][0] * SCALE : -1e9f;
            sf[g][1] = (qok0 && k1ok) ? sf[g][1] * SCALE : -1e9f;
            sf[g][2] = (qok1 && k0ok) ? sf[g][2] * SCALE : -1e9f;
            sf[g][3] = (qok1 && k1ok) ? sf[g][3] * SCALE : -1e9f;
            rmax0 = fmaxf(rmax0, fmaxf(sf[g][0], sf[g][1]));
            rmax1 = fmaxf(rmax1, fmaxf(sf[g][2], sf[g][3]));
        }
        rmax0 = fmaxf(rmax0, __shfl_xor_sync(0xffffffffu, rmax0, 1));
        rmax0 = fmaxf(rmax0, __shfl_xor_sync(0xffffffffu, rmax0, 2));
        rmax1 = fmaxf(rmax1, __shfl_xor_sync(0xffffffffu, rmax1, 1));
        rmax1 = fmaxf(rmax1, __shfl_xor_sync(0xffffffffu, rmax1, 2));
        float nm0 = fmaxf(mrow0, rmax0), nm1 = fmaxf(mrow1, rmax1);
        float ts0 = 0.f, ts1 = 0.f;
#pragma unroll
        for (int g = 0; g < 8; g++) {
            sf[g][0] = __expf(sf[g][0] - nm0);
            sf[g][1] = __expf(sf[g][1] - nm0);
            sf[g][2] = __expf(sf[g][2] - nm1);
            sf[g][3] = __expf(sf[g][3] - nm1);
            ts0 += sf[g][0] + sf[g][1];
            ts1 += sf[g][2] + sf[g][3];
        }
        ts0 += __shfl_xor_sync(0xffffffffu, ts0, 1);
        ts0 += __shfl_xor_sync(0xffffffffu, ts0, 2);
        ts1 += __shfl_xor_sync(0xffffffffu, ts1, 1);
        ts1 += __shfl_xor_sync(0xffffffffu, ts1, 2);
        float fac0 = __expf(mrow0 - nm0), fac1 = __expf(mrow1 - nm1);
        lrow0 = lrow0 * fac0 + ts0; mrow0 = nm0;
        lrow1 = lrow1 * fac1 + ts1; mrow1 = nm1;
#pragma unroll
        for (int g = 0; g < 4; g++) {
            oacc[g][0] *= fac0; oacc[g][1] *= fac0;
            oacc[g][2] *= fac1; oacc[g][3] *= fac1;
        }

        // ---- O += P V  (P as register A-fragments) ----
#pragma unroll
        for (int tk = 0; tk < 4; tk++) {
            uint32_t a0 = h2pack(sf[2 * tk][0],     sf[2 * tk][1]);
            uint32_t a1 = h2pack(sf[2 * tk][2],     sf[2 * tk][3]);
            uint32_t a2 = h2pack(sf[2 * tk + 1][0], sf[2 * tk + 1][1]);
            uint32_t a3 = h2pack(sf[2 * tk + 1][2], sf[2 * tk + 1][3]);
#pragma unroll
            for (int g2 = 0; g2 < 2; g2++) {
                uint32_t r0, r1, r2, r3;
                ldsm_x4(r0, r1, r2, r3,
                        VTB + (uint32_t)((buf * 32 * 72 + (g2 * 16 + bRow) * 72 + tk * 16 + bCol) * 2));
                mma_fp16(oacc[g2 * 2][0], oacc[g2 * 2][1], oacc[g2 * 2][2], oacc[g2 * 2][3],
                         a0, a1, a2, a3, r0, r1);
                mma_fp16(oacc[g2 * 2 + 1][0], oacc[g2 * 2 + 1][1], oacc[g2 * 2 + 1][2], oacc[g2 * 2 + 1][3],
                         a0, a1, a2, a3, r2, r3);
            }
        }

        __syncthreads();   // all reads of Ks/VTs[buf^1 writes target] done
        if (t < 7) {
            const int nb = buf ^ 1;
            *(uint4*)&Ks[nb][r4][u4 * 8]      = kpre[0];
            *(uint4*)&Ks[nb][r4 + 32][u4 * 8] = kpre[1];
#pragma unroll
            for (int jj = 0; jj < 8; jj++) {
                int idx = tid + jj * 128;
                int d2 = idx & 15, jrow = idx >> 4;
                VTs[nb][d2 * 2][jrow]     = vpre[jj].x;
                VTs[nb][d2 * 2 + 1][jrow] = vpre[jj].y;
            }
            if (tid < 64) vks[nb][tid] = vkpre;
            __syncthreads();
        }
    }

    // ---- finalize: O / l ----
    float inv0 = 1.f / lrow0, inv1 = 1.f / lrow1;
    const int row0 = qt * 64 + wid * 16 + lr;
    const int colb = h * DKn + (lane & 3) * 2;
#pragma unroll
    for (int g = 0; g < 4; g++) {
        long long base0 = ((long long)b * Ln + row0)     * Dn + colb + g * 8;
        long long base1 = ((long long)b * Ln + row0 + 8) * Dn + colb + g * 8;
        *(__half2*)(ctx + base0) = __floats2half2_rn(oacc[g][0] * inv0, oacc[g][1] * inv0);
        *(__half2*)(ctx + base1) = __floats2half2_rn(oacc[g][2] * inv1, oacc[g][3] * inv1);
    }
}

// ---------------------------------------------------------------------------
// Host launcher
// ---------------------------------------------------------------------------
extern "C" void kernel_launch(void* const* d_in, const int* in_sizes, int n_in,
                              void* d_out, int out_size)
{
    const float* x_a = (const float*)d_in[0];
    const float* x_b = (const float*)d_in[1];
    const unsigned int* valid_a = (const unsigned int*)d_in[2];
    const unsigned int* valid_b = (const unsigned int*)d_in[3];
    const float* ln_a_g  = (const float*)d_in[4];
    const float* ln_a_b  = (const float*)d_in[5];
    const float* ln_b_g  = (const float*)d_in[6];
    const float* ln_b_b  = (const float*)d_in[7];
    const float* ln_oa_g = (const float*)d_in[8];
    const float* ln_oa_b = (const float*)d_in[9];
    const float* ln_ob_g = (const float*)d_in[10];
    const float* ln_ob_b = (const float*)d_in[11];
    const float* wq = (const float*)d_in[12];
    const float* bq = (const float*)d_in[13];
    const float* wk = (const float*)d_in[14];
    const float* bk = (const float*)d_in[15];
    const float* wv = (const float*)d_in[16];
    const float* bv = (const float*)d_in[17];
    const float* wo = (const float*)d_in[18];
    const float* bo = (const float*)d_in[19];
    const float* fln_g  = (const float*)d_in[20];
    const float* fln_b  = (const float*)d_in[21];
    const float* flno_g = (const float*)d_in[22];
    const float* flno_b = (const float*)d_in[23];
    const float* w1 = (const float*)d_in[24];
    const float* b1 = (const float*)d_in[25];
    const float* w2 = (const float*)d_in[26];
    const float* b2 = (const float*)d_in[27];

    float* ws = nullptr;
    cudaGetSymbolAddress((void**)&ws, g_ws);
    __half* wh = nullptr;
    cudaGetSymbolAddress((void**)&wh, g_wsh);

    float* tmpa = ws + 0 * BLD;
    float* tmpb = ws + 1 * BLD;
    float* oa   = ws + 2 * BLD;
    float* ob   = ws + 3 * BLD;
    float* yba  = ws + 4 * BLD;
    float* ybb  = ws + 5 * BLD;

    __half* alnH  = wh + OFF_ALN;
    __half* blnH  = wh + OFF_BLN;
    __half* ctxaH = wh + OFF_CTXA;
    __half* ctxbH = wh + OFF_CTXB;
    __half* xnaH  = wh + OFF_XNA;
    __half* xnbH  = wh + OFF_XNB;
    __half* QaH   = wh + OFF_QA;
    __half* KaH   = wh + OFF_KA;
    __half* VaH   = wh + OFF_VA;
    __half* QbH   = wh + OFF_QB;
    __half* KbH   = wh + OFF_KB;
    __half* VbH   = wh + OFF_VB;
    __half* hidaH = wh + OFF_HIDA;
    __half* hidbH = wh + OFF_HIDB;
    __half* wqH   = wh + OFF_WQ;
    __half* wkH   = wh + OFF_WK;
    __half* wvH   = wh + OFF_WV;
    __half* woH   = wh + OFF_WO;
    __half* w1H   = wh + OFF_W1;
    __half* w2H   = wh + OFF_W2;

    float* out_a = (float*)d_out;
    float* out_b = (float*)d_out + BLD;

    dim3 blk(256);
    dim3 gLN(ROWS / 8);

    // 0. weight conversions
    {
        int nDD = Dn * Dn;
        wconv_kernel<<<(nDD + 255) / 256, blk>>>(wq, wqH, Dn, Dn);
        wconv_kernel<<<(nDD + 255) / 256, blk>>>(wk, wkH, Dn, Dn);
        wconv_kernel<<<(nDD + 255) / 256, blk>>>(wv, wvH, Dn, Dn);
        wconv_kernel<<<(nDD + 255) / 256, blk>>>(wo, woH, Dn, Dn);
        int nDH = Dn * HIDn;
        wconv_kernel<<<(nDH + 255) / 256, blk>>>(w1, w1H, Dn, HIDn);
        wconv_kernel<<<(nDH + 255) / 256, blk>>>(w2, w2H, HIDn, Dn);
    }

    // 1. pre-attention masked LN -> fp16 operands
    mln_kernel<<<gLN, blk>>>(x_a, nullptr, valid_a, ln_a_g, ln_a_b, nullptr, alnH);
    mln_kernel<<<gLN, blk>>>(x_b, nullptr, valid_b, ln_b_g, ln_b_b, nullptr, blnH);

    // 2. six projections -> fp16 Q/K/V (EPI=2)
    {
        TcBatch tb;
        tb.A[0] = alnH; tb.A[1] = alnH; tb.A[2] = alnH;
        tb.A[3] = blnH; tb.A[4] = blnH; tb.A[5] = blnH;
        tb.B[0] = wqH;  tb.B[1] = wkH;  tb.B[2] = wvH;
        tb.B[3] = wqH;  tb.B[4] = wkH;  tb.B[5] = wvH;
        tb.bias[0] = bq; tb.bias[1] = bk; tb.bias[2] = bv;
        tb.bias[3] = bq; tb.bias[4] = bk; tb.bias[5] = bv;
        tb.C[0] = QaH; tb.C[1] = KaH; tb.C[2] = VaH;
        tb.C[3] = QbH; tb.C[4] = KbH; tb.C[5] = VbH;
        dim3 grid(ROWS / 128, Dn / 64, 6);
        mma_gemm_kernel<2><<<grid, blk>>>(tb, Dn, Dn);
    }

    // 3. flash attention (tensor cores) -> fp16 ctx
    {
        FlashArgs fa;
        fa.Q[0] = QaH; fa.K[0] = KbH; fa.V[0] = VbH; fa.vq[0] = valid_a; fa.vk[0] = valid_b; fa.ctx[0] = ctxaH;
        fa.Q[1] = QbH; fa.K[1] = KaH; fa.V[1] = VaH; fa.vq[1] = valid_b; fa.vk[1] = valid_a; fa.ctx[1] = ctxbH;
        dim3 grid(Ln / 64, Bn * Hn, 2);
        flash_mma_kernel<<<grid, 128>>>(fa);
    }

    // 4. output projection + fused residual-LN + pre-FFN LN
    {
        TcBatch tb = {};
        tb.A[0] = ctxaH; tb.A[1] = ctxbH;
        tb.B[0] = woH;   tb.B[1] = woH;
        tb.bias[0] = bo; tb.bias[1] = bo;
        tb.C[0] = tmpa;  tb.C[1] = tmpb;
        dim3 grid(ROWS / 128, Dn / 64, 2);
        mma_gemm_kernel<0><<<grid, blk>>>(tb, Dn, Dn);
    }
    mln2_kernel<<<gLN, blk>>>(tmpa, x_a, valid_a, ln_oa_g, ln_oa_b, fln_g, fln_b, oa, xnaH);
    mln2_kernel<<<gLN, blk>>>(tmpb, x_b, valid_b, ln_ob_g, ln_ob_b, fln_g, fln_b, ob, xnbH);

    // 5. FFN w1 + GELU -> fp16 hid
    {
        TcBatch tb = {};
        tb.A[0] = xnaH; tb.A[1] = xnbH;
        tb.B[0] = w1H;  tb.B[1] = w1H;
        tb.bias[0] = b1; tb.bias[1] = b1;
        tb.C[0] = hidaH; tb.C[1] = hidbH;
        dim3 grid(ROWS / 128, HIDn / 64, 2);
        mma_gemm_kernel<1><<<grid, blk>>>(tb, Dn, HIDn);
    }
    // 6. FFN w2
    {
        TcBatch tb = {};
        tb.A[0] = hidaH; tb.A[1] = hidbH;
        tb.B[0] = w2H;   tb.B[1] = w2H;
        tb.bias[0] = b2; tb.bias[1] = b2;
        tb.C[0] = yba;   tb.C[1] = ybb;
        dim3 grid(ROWS / 128, Dn / 64, 2);
        mma_gemm_kernel<0><<<grid, blk>>>(tb, HIDn, Dn);
    }
    // 7. final masked LN (+residual) -> fp32 outputs
    mln_kernel<<<gLN, blk>>>(yba, oa, valid_a, flno_g, flno_b, out_a, nullptr);
    mln_kernel<<<gLN, blk>>>(ybb, ob, valid_b, flno_g, flno_b, out_b, nullptr);
}